// round 11
// baseline (speedup 1.0000x reference)
#include <cuda_runtime.h>

#define NCELLS   19683
#define KNB      26
#define ROWS     72    // rows per CTA tile  -> grid 274 (single wave @ 2 CTA/SM)
#define NTHREADS 192   // 16 tx x 12 ty, 6 rows per thread
#define RPT      6     // rows per thread
#define XP       132   // Xs row pitch (floats)
#define WPP      132   // Ws row pitch (floats)
#define GSB      100   // Gs column base inside Ws rows (cols 100..131, unused by Wl)

// ---------------- scratch (device globals: allocation-free) ----------------
__device__ float g_mean_l[NCELLS * 64];
__device__ float g_mean_f[NCELLS * 64];
__device__ float g_mean_d[NCELLS * 64];
__device__ float g_act[NCELLS * 64];
__device__ int   g_flags[NCELLS];

typedef unsigned long long ull;

__device__ __forceinline__ ull pack2(float x, float y) {
    ull r; asm("mov.b64 %0, {%1,%2};" : "=l"(r) : "f"(x), "f"(y)); return r;
}
__device__ __forceinline__ float2 unpack2(ull v) {
    float2 r; asm("mov.b64 {%0,%1}, %2;" : "=f"(r.x), "=f"(r.y) : "l"(v)); return r;
}
__device__ __forceinline__ void ffma2(ull& acc, ull a, ull b) {
    asm("fma.rn.f32x2 %0, %1, %2, %0;" : "+l"(acc) : "l"(a), "l"(b));
}

// branchless tanh: 2 MUFU + few FMA, no divergence, rel err ~1e-6
__device__ __forceinline__ float fast_tanh(float x) {
    float ax = fabsf(x);
    float t  = __expf(-2.0f * ax);            // in (0,1], never overflows
    float r  = __fdividef(1.0f - t, 1.0f + t);
    return copysignf(r, x);
}

// ---------------- cp.async helpers ----------------
__device__ __forceinline__ void cpa16(void* s, const void* g) {
    unsigned sa = (unsigned)__cvta_generic_to_shared(s);
    asm volatile("cp.async.ca.shared.global [%0], [%1], 16;" :: "r"(sa), "l"(g));
}
__device__ __forceinline__ void cpa16z(void* s, const void* g, int srcbytes) {
    unsigned sa = (unsigned)__cvta_generic_to_shared(s);
    asm volatile("cp.async.ca.shared.global [%0], [%1], 16, %2;"
                 :: "r"(sa), "l"(g), "r"(srcbytes));
}
__device__ __forceinline__ void cp_wait_all() {
    asm volatile("cp.async.wait_all;" ::: "memory");
}

// ---------------- kernel A: masked neighbor aggregation (branch-free) ------
__global__ void agg_kernel(const float* __restrict__ nb, const int* __restrict__ cat) {
    int gw = (blockIdx.x * blockDim.x + threadIdx.x) >> 5;
    if (gw >= NCELLS) return;
    int lane = threadIdx.x & 31;
    const float* base = nb + (size_t)gw * (KNB * 64);
    int myc = (lane < KNB) ? cat[gw * KNB + lane] : -1;

    unsigned m0 = __ballot_sync(0xffffffffu, myc == 0);
    unsigned m1 = __ballot_sync(0xffffffffu, myc == 1);
    unsigned m2 = __ballot_sync(0xffffffffu, myc == 2);

    float2 s0 = {0.f, 0.f}, s1 = {0.f, 0.f}, s2 = {0.f, 0.f}, sa = {0.f, 0.f};
#pragma unroll
    for (int k = 0; k < KNB; k++) {
        float2 v = *(const float2*)(base + k * 64 + lane * 2);
        sa.x += v.x; sa.y += v.y;
        bool b0 = (m0 >> k) & 1u;
        bool b1 = (m1 >> k) & 1u;
        bool b2 = (m2 >> k) & 1u;
        s0.x += b0 ? v.x : 0.f;  s0.y += b0 ? v.y : 0.f;
        s1.x += b1 ? v.x : 0.f;  s1.y += b1 ? v.y : 0.f;
        s2.x += b2 ? v.x : 0.f;  s2.y += b2 ? v.y : 0.f;
    }
    int c0 = __popc(m0), c1 = __popc(m1), c2 = __popc(m2);
    float d0 = fmaxf((float)c0, 1.0f);
    float d1 = fmaxf((float)c1, 1.0f);
    float d2 = fmaxf((float)c2, 1.0f);
    int off = gw * 64 + lane * 2;
    *(float2*)(g_mean_l + off) = make_float2(s0.x / d0, s0.y / d0);
    *(float2*)(g_mean_f + off) = make_float2(s1.x / d1, s1.y / d1);
    *(float2*)(g_mean_d + off) = make_float2(s2.x / d2, s2.y / d2);
    *(float2*)(g_act    + off) = make_float2(sa.x / 26.0f, sa.y / 26.0f);
    if (lane == 0)
        g_flags[gw] = (c0 > 0 ? 1 : 0) | (c1 > 0 ? 2 : 0) | (c2 > 0 ? 4 : 0);
}

// ---------------- kernel B helpers (async) ----------------
template <int NC>
__device__ __forceinline__ void loadW_async(const float* __restrict__ Wg, float* Ws, int tid) {
    constexpr int PR = NC / 4;  // float4 per row
    for (int i = tid; i < 128 * PR; i += NTHREADS) {
        int r = i / PR, c = i % PR;
        cpa16(&Ws[r * WPP + c * 4], Wg + 4 * i);
    }
}

// async fill Xs = [L | R]
__device__ __forceinline__ void fillX_async(float* Xs, const float* __restrict__ L,
                                            const float* __restrict__ R,
                                            int tid, int base, int nrows) {
#pragma unroll
    for (int i = tid; i < ROWS * 32; i += NTHREADS) {  // 12 iters exact
        int r = i >> 5;
        int c4 = i & 31;
        int gr = base + ((r < nrows) ? r : 0);
        const float* src = (c4 < 16) ? (L + (size_t)gr * 64 + (c4 << 2))
                                     : (R + (size_t)gr * 64 + ((c4 - 16) << 2));
        cpa16z(&Xs[r * XP + (c4 << 2)], src, (r < nrows) ? 16 : 0);
    }
}

// async fill only right half of Xs from R
__device__ __forceinline__ void fillXright_async(float* Xs, const float* __restrict__ R,
                                                 int tid, int base, int nrows) {
#pragma unroll
    for (int i = tid; i < ROWS * 16; i += NTHREADS) {  // 6 iters exact
        int r = i >> 4;
        int c4 = i & 15;
        int gr = base + ((r < nrows) ? r : 0);
        cpa16z(&Xs[r * XP + 64 + (c4 << 2)], R + (size_t)gr * 64 + (c4 << 2),
               (r < nrows) ? 16 : 0);
    }
}

// GEMM over K=128; fragment = RPT rows x TC cols per thread, packed f32x2 FMAs.
// TC=8 uses SPLIT column groups (tx*4 and 64+tx*4): LDS.128 at tx*16B strides
// keeps every 8-lane phase inside one 128B line set -> conflict-free, whereas
// the old tx*32B stride aliased lanes tx and tx+4 (2-way conflict).
template <int TC>
__device__ __forceinline__ void gemm128(const float* __restrict__ Xs,
                                        const float* __restrict__ Ws,
                                        int r0, int tx, ull (&acc)[RPT][TC / 2]) {
#pragma unroll
    for (int i = 0; i < RPT; i++)
#pragma unroll
        for (int j = 0; j < TC / 2; j++) acc[i][j] = 0ULL;

#pragma unroll 2
    for (int k = 0; k < 128; k += 4) {
        float4 a[RPT];
#pragma unroll
        for (int i = 0; i < RPT; i++) a[i] = *(const float4*)&Xs[(r0 + i) * XP + k];
#pragma unroll
        for (int kk = 0; kk < 4; kk++) {
            ull b[TC / 2];
            if constexpr (TC == 8) {
                const float* bpa = &Ws[(k + kk) * WPP + tx * 4];
                const float* bpb = &Ws[(k + kk) * WPP + 64 + tx * 4];
                ulonglong2 q0 = *(const ulonglong2*)bpa;
                ulonglong2 q1 = *(const ulonglong2*)bpb;
                b[0] = q0.x; b[1] = q0.y; b[2] = q1.x; b[3] = q1.y;
            } else if constexpr (TC == 4) {
                const float* bp = &Ws[(k + kk) * WPP + tx * 4];
                ulonglong2 q0 = *(const ulonglong2*)bp;
                b[0] = q0.x; b[1] = q0.y;
            } else {
                const float* bp = &Ws[(k + kk) * WPP + tx * 2];
                b[0] = *(const ull*)bp;
            }
#pragma unroll
            for (int i = 0; i < RPT; i++) {
                float av = ((const float*)&a[i])[kk];
                ull ap = pack2(av, av);
#pragma unroll
                for (int j = 0; j < TC / 2; j++) ffma2(acc[i][j], ap, b[j]);
            }
        }
    }
}

// ---------------- kernel B: fused MoE MLP stack (cp.async pipelined) -------
__global__ void __launch_bounds__(NTHREADS, 2)
moe_kernel(const float* __restrict__ cur,
           const float* __restrict__ Wl,  const float* __restrict__ bl,
           const float* __restrict__ Wf1, const float* __restrict__ bf1,
           const float* __restrict__ Wf2, const float* __restrict__ bf2,
           const float* __restrict__ Wc1, const float* __restrict__ bc1,
           const float* __restrict__ Wc2, const float* __restrict__ bc2,
           const float* __restrict__ Wg1, const float* __restrict__ bg1,
           const float* __restrict__ Wg2, const float* __restrict__ bg2,
           float* __restrict__ out, int out_size) {
    extern __shared__ float sm[];
    float* Xs    = sm;                       // [ROWS][XP]
    float* Ws    = Xs + ROWS * XP;           // [128][WPP]  (Gs in cols GSB..GSB+31)
    float* sw    = Ws + 128 * WPP;           // [ROWS][4]
    int*   sflag = (int*)(sw + ROWS * 4);    // [ROWS]

    int tid  = threadIdx.x;
    int base = blockIdx.x * ROWS;
    int nrows = min(ROWS, NCELLS - base);

    int tx = tid & 15;          // 0..15 (column group)
    int ty = tid >> 4;          // 0..11 (row group)
    int r0 = ty * RPT;

    // ================= prologue: gating inputs =================
    fillX_async(Xs, cur, g_act, tid, base, nrows);
    loadW_async<32>(Wg1, Ws, tid);
    if (tid < ROWS)
        sflag[tid] = (base + tid < NCELLS) ? g_flags[base + tid] : 0;
    cp_wait_all();
    __syncthreads();

    // ================= gating =================
    ull ag[RPT][1];
    gemm128<2>(Xs, Ws, r0, tx, ag);
    __syncthreads();           // all Xs/Ws reads done

    // prefetch local-expert data while writing Gs + reducing
    fillXright_async(Xs, g_mean_l, tid, base, nrows);   // Xs cols 64..127
    loadW_async<64>(Wl, Ws, tid);                       // Ws cols 0..63
    {
        float2 bg = *(const float2*)&bg1[tx * 2];
#pragma unroll
        for (int i = 0; i < RPT; i++) {
            int row = r0 + i;
            float2 v = unpack2(ag[i][0]);
            int k0 = tx * 2;
            Ws[row * WPP + GSB + ((k0 + row) & 31)]     = fast_tanh(v.x + bg.x);
            Ws[row * WPP + GSB + ((k0 + 1 + row) & 31)] = fast_tanh(v.y + bg.y);
        }
    }
    __syncthreads();
    if (tid < ROWS) {
        int row = tid;
        float l0 = bg2[0], l1 = bg2[1], l2 = bg2[2];
#pragma unroll
        for (int k = 0; k < 32; k++) {
            float gv = Ws[row * WPP + GSB + ((k + row) & 31)];
            l0 += gv * Wg2[k * 3 + 0];
            l1 += gv * Wg2[k * 3 + 1];
            l2 += gv * Wg2[k * 3 + 2];
        }
        float m = fmaxf(l0, fmaxf(l1, l2));
        float e0 = expf(l0 - m), e1 = expf(l1 - m), e2 = expf(l2 - m);
        float inv = 1.0f / (e0 + e1 + e2);
        float w0 = e0 * inv, w1 = e1 * inv, w2 = e2 * inv;
        sw[row * 4 + 0] = w0; sw[row * 4 + 1] = w1; sw[row * 4 + 2] = w2;
        int gr = base + row;
        if (gr < NCELLS && out_size >= NCELLS * 67) {
            out[(size_t)NCELLS * 64 + (size_t)gr * 3 + 0] = w0;
            out[(size_t)NCELLS * 64 + (size_t)gr * 3 + 1] = w1;
            out[(size_t)NCELLS * 64 + (size_t)gr * 3 + 2] = w2;
        }
    }
    cp_wait_all();
    __syncthreads();

    float2 comb[RPT][2];

    // ================= local expert =================
    {
        ull al[RPT][2];
        gemm128<4>(Xs, Ws, r0, tx, al);
        __syncthreads();       // Xs/Ws reads done
        // prefetch functional-expert data during epilogue
        fillXright_async(Xs, g_mean_f, tid, base, nrows);
        loadW_async<128>(Wf1, Ws, tid);
        float2 b0 = *(const float2*)&bl[tx * 4];
        float2 b1 = *(const float2*)&bl[tx * 4 + 2];
#pragma unroll
        for (int i = 0; i < RPT; i++) {
            int row = r0 + i;
            float w0 = sw[row * 4 + 0];
            bool on = (sflag[row] & 1);
            float2 v0 = unpack2(al[i][0]);
            float2 v1 = unpack2(al[i][1]);
            comb[i][0].x = on ? w0 * fast_tanh(v0.x + b0.x) : 0.f;
            comb[i][0].y = on ? w0 * fast_tanh(v0.y + b0.y) : 0.f;
            comb[i][1].x = on ? w0 * fast_tanh(v1.x + b1.x) : 0.f;
            comb[i][1].y = on ? w0 * fast_tanh(v1.y + b1.y) : 0.f;
        }
        cp_wait_all();
        __syncthreads();
    }

    // ================= functional expert =================
    {
        ull ah[RPT][4];
        gemm128<8>(Xs, Ws, r0, tx, ah);
        __syncthreads();       // all threads done reading Xs/Ws
        loadW_async<64>(Wf2, Ws, tid);   // overlaps tanh(h) epilogue
        // split column groups: ah[i][0..1] -> cols tx*4.., ah[i][2..3] -> cols 64+tx*4..
        float4 b0 = *(const float4*)&bf1[tx * 4];
        float4 b1 = *(const float4*)&bf1[64 + tx * 4];
#pragma unroll
        for (int i = 0; i < RPT; i++) {
            float2 v0 = unpack2(ah[i][0]), v1 = unpack2(ah[i][1]);
            float2 v2 = unpack2(ah[i][2]), v3 = unpack2(ah[i][3]);
            float4 o0 = make_float4(fast_tanh(v0.x + b0.x), fast_tanh(v0.y + b0.y),
                                    fast_tanh(v1.x + b0.z), fast_tanh(v1.y + b0.w));
            float4 o1 = make_float4(fast_tanh(v2.x + b1.x), fast_tanh(v2.y + b1.y),
                                    fast_tanh(v3.x + b1.z), fast_tanh(v3.y + b1.w));
            *(float4*)&Xs[(r0 + i) * XP + tx * 4]      = o0;
            *(float4*)&Xs[(r0 + i) * XP + 64 + tx * 4] = o1;
        }
        cp_wait_all();
        __syncthreads();
    }
    float2 x[RPT][2];
    {
        ull af[RPT][2];
        gemm128<4>(Xs, Ws, r0, tx, af);
        __syncthreads();       // Xs/Ws reads done
        // prefetch CNF step-0 data during epilogue
        loadW_async<128>(Wc1, Ws, tid);
        fillXright_async(Xs, g_mean_d, tid, base, nrows);
        float2 c0 = *(const float2*)&bf2[tx * 4];
        float2 c1 = *(const float2*)&bf2[tx * 4 + 2];
#pragma unroll
        for (int i = 0; i < RPT; i++) {
            int row = r0 + i;
            float w1 = sw[row * 4 + 1];
            bool on = (sflag[row] & 2);
            float2 v0 = unpack2(af[i][0]);
            float2 v1 = unpack2(af[i][1]);
            comb[i][0].x += on ? w1 * fast_tanh(v0.x + c0.x) : 0.f;
            comb[i][0].y += on ? w1 * fast_tanh(v0.y + c0.y) : 0.f;
            comb[i][1].x += on ? w1 * fast_tanh(v1.x + c1.x) : 0.f;
            comb[i][1].y += on ? w1 * fast_tanh(v1.y + c1.y) : 0.f;
        }
        // CNF x init (plain LDG, overlaps copies) + stage x into Xs left half
#pragma unroll
        for (int i = 0; i < RPT; i++) {
            int gr = base + r0 + i;
            float4 cv = make_float4(0.f, 0.f, 0.f, 0.f);
            if (gr < NCELLS) cv = *(const float4*)(cur + (size_t)gr * 64 + tx * 4);
            x[i][0] = make_float2(cv.x, cv.y);
            x[i][1] = make_float2(cv.z, cv.w);
            *(float4*)&Xs[(r0 + i) * XP + tx * 4] = cv;
        }
        cp_wait_all();
        __syncthreads();
    }

    // ================= distant expert (CNF, 3 Euler steps) =================
    // loop invariant at top: Xs = [x | mean_d] valid, Ws = Wc1 valid, synced
    const float DT = 1.0f / 3.0f;
    for (int step = 0; step < 3; step++) {
        ull av[RPT][4];
        gemm128<8>(Xs, Ws, r0, tx, av);
        __syncthreads();
        loadW_async<64>(Wc2, Ws, tid);   // overlaps tanh(v) epilogue
        {
            float4 b0 = *(const float4*)&bc1[tx * 4];
            float4 b1 = *(const float4*)&bc1[64 + tx * 4];
#pragma unroll
            for (int i = 0; i < RPT; i++) {
                float2 v0 = unpack2(av[i][0]), v1 = unpack2(av[i][1]);
                float2 v2 = unpack2(av[i][2]), v3 = unpack2(av[i][3]);
                float4 o0 = make_float4(fast_tanh(v0.x + b0.x), fast_tanh(v0.y + b0.y),
                                        fast_tanh(v1.x + b0.z), fast_tanh(v1.y + b0.w));
                float4 o1 = make_float4(fast_tanh(v2.x + b1.x), fast_tanh(v2.y + b1.y),
                                        fast_tanh(v3.x + b1.z), fast_tanh(v3.y + b1.w));
                *(float4*)&Xs[(r0 + i) * XP + tx * 4]      = o0;
                *(float4*)&Xs[(r0 + i) * XP + 64 + tx * 4] = o1;
            }
        }
        cp_wait_all();
        __syncthreads();
        ull ad[RPT][2];
        gemm128<4>(Xs, Ws, r0, tx, ad);
        __syncthreads();
        if (step < 2) {
            loadW_async<128>(Wc1, Ws, tid);            // next step's weights
            fillXright_async(Xs, g_mean_d, tid, base, nrows);  // restore mean_d
        }
        {
            float2 c0 = *(const float2*)&bc2[tx * 4];
            float2 c1 = *(const float2*)&bc2[tx * 4 + 2];
#pragma unroll
            for (int i = 0; i < RPT; i++) {
                float2 v0 = unpack2(ad[i][0]);
                float2 v1 = unpack2(ad[i][1]);
                x[i][0].x += DT * fast_tanh(v0.x + c0.x);
                x[i][0].y += DT * fast_tanh(v0.y + c0.y);
                x[i][1].x += DT * fast_tanh(v1.x + c1.x);
                x[i][1].y += DT * fast_tanh(v1.y + c1.y);
            }
        }
        if (step < 2) {
            // stage updated x into Xs left half for next step
#pragma unroll
            for (int i = 0; i < RPT; i++) {
                float4 xv = make_float4(x[i][0].x, x[i][0].y, x[i][1].x, x[i][1].y);
                *(float4*)&Xs[(r0 + i) * XP + tx * 4] = xv;
            }
            cp_wait_all();
            __syncthreads();
        }
    }
#pragma unroll
    for (int i = 0; i < RPT; i++) {
        int row = r0 + i;
        float w2 = sw[row * 4 + 2];
        bool on = (sflag[row] & 4);
        comb[i][0].x += on ? w2 * x[i][0].x : 0.f;
        comb[i][0].y += on ? w2 * x[i][0].y : 0.f;
        comb[i][1].x += on ? w2 * x[i][1].x : 0.f;
        comb[i][1].y += on ? w2 * x[i][1].y : 0.f;
    }

    // ================= store combined =================
#pragma unroll
    for (int i = 0; i < RPT; i++) {
        int gr = base + r0 + i;
        if (gr < NCELLS) {
            float4 o = make_float4(comb[i][0].x, comb[i][0].y,
                                   comb[i][1].x, comb[i][1].y);
            *(float4*)&out[(size_t)gr * 64 + tx * 4] = o;
        }
    }
}

// ---------------- launch ----------------
extern "C" void kernel_launch(void* const* d_in, const int* in_sizes, int n_in,
                              void* d_out, int out_size) {
    const float* cur = (const float*)d_in[0];
    const float* nb  = (const float*)d_in[1];
    const int*   cat = (const int*)d_in[2];
    const float* Wl  = (const float*)d_in[3];
    const float* bl  = (const float*)d_in[4];
    const float* Wf1 = (const float*)d_in[5];
    const float* bf1 = (const float*)d_in[6];
    const float* Wf2 = (const float*)d_in[7];
    const float* bf2 = (const float*)d_in[8];
    const float* Wc1 = (const float*)d_in[9];
    const float* bc1 = (const float*)d_in[10];
    const float* Wc2 = (const float*)d_in[11];
    const float* bc2 = (const float*)d_in[12];
    const float* Wg1 = (const float*)d_in[13];
    const float* bg1 = (const float*)d_in[14];
    const float* Wg2 = (const float*)d_in[15];
    const float* bg2 = (const float*)d_in[16];
    float* out = (float*)d_out;

    const int smem_bytes = (ROWS * XP + 128 * WPP + ROWS * 4 + ROWS) * 4;
    cudaFuncSetAttribute(moe_kernel, cudaFuncAttributeMaxDynamicSharedMemorySize,
                         smem_bytes);

    int agg_blocks = (NCELLS * 32 + 255) / 256;
    agg_kernel<<<agg_blocks, 256>>>(nb, cat);

    int moe_blocks = (NCELLS + ROWS - 1) / ROWS;   // 274 -> single wave at 2 CTA/SM
    moe_kernel<<<moe_blocks, NTHREADS, smem_bytes>>>(
        cur, Wl, bl, Wf1, bf1, Wf2, bf2, Wc1, bc1, Wc2, bc2,
        Wg1, bg1, Wg2, bg2, out, out_size);
}

// round 13
// speedup vs baseline: 1.0822x; 1.0822x over previous
#include <cuda_runtime.h>

#define NCELLS   19683
#define KNB      26
#define ROWS     80    // rows per CTA tile  -> grid 247 (single wave @ 2 CTA/SM)
#define NTHREADS 256   // 16 tx x 16 ty -> 8 warps: SMSP-balanced
#define RPT      5     // rows per thread
#define XP       132   // Xs row pitch (floats)
#define WPP      132   // Ws row pitch (floats)
#define GSB      100   // Gs column base inside Ws rows (cols 100..131, unused by Wl)

// ---------------- scratch (device globals: allocation-free) ----------------
__device__ float g_mean_l[NCELLS * 64];
__device__ float g_mean_f[NCELLS * 64];
__device__ float g_mean_d[NCELLS * 64];
__device__ float g_act[NCELLS * 64];
__device__ int   g_flags[NCELLS];

typedef unsigned long long ull;

__device__ __forceinline__ ull pack2(float x, float y) {
    ull r; asm("mov.b64 %0, {%1,%2};" : "=l"(r) : "f"(x), "f"(y)); return r;
}
__device__ __forceinline__ float2 unpack2(ull v) {
    float2 r; asm("mov.b64 {%0,%1}, %2;" : "=f"(r.x), "=f"(r.y) : "l"(v)); return r;
}
__device__ __forceinline__ void ffma2(ull& acc, ull a, ull b) {
    asm("fma.rn.f32x2 %0, %1, %2, %0;" : "+l"(acc) : "l"(a), "l"(b));
}

// branchless tanh: 2 MUFU + few FMA, no divergence, rel err ~1e-6
__device__ __forceinline__ float fast_tanh(float x) {
    float ax = fabsf(x);
    float t  = __expf(-2.0f * ax);
    float r  = __fdividef(1.0f - t, 1.0f + t);
    return copysignf(r, x);
}

// ---------------- cp.async helpers ----------------
__device__ __forceinline__ void cpa16(void* s, const void* g) {
    unsigned sa = (unsigned)__cvta_generic_to_shared(s);
    asm volatile("cp.async.ca.shared.global [%0], [%1], 16;" :: "r"(sa), "l"(g));
}
__device__ __forceinline__ void cpa16z(void* s, const void* g, int srcbytes) {
    unsigned sa = (unsigned)__cvta_generic_to_shared(s);
    asm volatile("cp.async.ca.shared.global [%0], [%1], 16, %2;"
                 :: "r"(sa), "l"(g), "r"(srcbytes));
}
__device__ __forceinline__ void cp_wait_all() {
    asm volatile("cp.async.wait_all;" ::: "memory");
}

// ---------------- kernel A: masked neighbor aggregation (branch-free) ------
__global__ void agg_kernel(const float* __restrict__ nb, const int* __restrict__ cat) {
    int gw = (blockIdx.x * blockDim.x + threadIdx.x) >> 5;
    if (gw >= NCELLS) return;
    int lane = threadIdx.x & 31;
    const float* base = nb + (size_t)gw * (KNB * 64);
    int myc = (lane < KNB) ? cat[gw * KNB + lane] : -1;

    unsigned m0 = __ballot_sync(0xffffffffu, myc == 0);
    unsigned m1 = __ballot_sync(0xffffffffu, myc == 1);
    unsigned m2 = __ballot_sync(0xffffffffu, myc == 2);

    float2 s0 = {0.f, 0.f}, s1 = {0.f, 0.f}, s2 = {0.f, 0.f}, sa = {0.f, 0.f};
#pragma unroll
    for (int k = 0; k < KNB; k++) {
        float2 v = *(const float2*)(base + k * 64 + lane * 2);
        sa.x += v.x; sa.y += v.y;
        bool b0 = (m0 >> k) & 1u;
        bool b1 = (m1 >> k) & 1u;
        bool b2 = (m2 >> k) & 1u;
        s0.x += b0 ? v.x : 0.f;  s0.y += b0 ? v.y : 0.f;
        s1.x += b1 ? v.x : 0.f;  s1.y += b1 ? v.y : 0.f;
        s2.x += b2 ? v.x : 0.f;  s2.y += b2 ? v.y : 0.f;
    }
    int c0 = __popc(m0), c1 = __popc(m1), c2 = __popc(m2);
    float d0 = fmaxf((float)c0, 1.0f);
    float d1 = fmaxf((float)c1, 1.0f);
    float d2 = fmaxf((float)c2, 1.0f);
    int off = gw * 64 + lane * 2;
    *(float2*)(g_mean_l + off) = make_float2(s0.x / d0, s0.y / d0);
    *(float2*)(g_mean_f + off) = make_float2(s1.x / d1, s1.y / d1);
    *(float2*)(g_mean_d + off) = make_float2(s2.x / d2, s2.y / d2);
    *(float2*)(g_act    + off) = make_float2(sa.x / 26.0f, sa.y / 26.0f);
    if (lane == 0)
        g_flags[gw] = (c0 > 0 ? 1 : 0) | (c1 > 0 ? 2 : 0) | (c2 > 0 ? 4 : 0);
}

// ---------------- kernel B helpers (async) ----------------
template <int NC>
__device__ __forceinline__ void loadW_async(const float* __restrict__ Wg, float* Ws, int tid) {
    constexpr int PR = NC / 4;  // float4 per row
    for (int i = tid; i < 128 * PR; i += NTHREADS) {
        int r = i / PR, c = i % PR;
        cpa16(&Ws[r * WPP + c * 4], Wg + 4 * i);
    }
}

// async fill Xs = [L | R]
__device__ __forceinline__ void fillX_async(float* Xs, const float* __restrict__ L,
                                            const float* __restrict__ R,
                                            int tid, int base, int nrows) {
#pragma unroll
    for (int i = tid; i < ROWS * 32; i += NTHREADS) {  // 10 iters exact
        int r = i >> 5;
        int c4 = i & 31;
        int gr = base + ((r < nrows) ? r : 0);
        const float* src = (c4 < 16) ? (L + (size_t)gr * 64 + (c4 << 2))
                                     : (R + (size_t)gr * 64 + ((c4 - 16) << 2));
        cpa16z(&Xs[r * XP + (c4 << 2)], src, (r < nrows) ? 16 : 0);
    }
}

// async fill only right half of Xs from R
__device__ __forceinline__ void fillXright_async(float* Xs, const float* __restrict__ R,
                                                 int tid, int base, int nrows) {
#pragma unroll
    for (int i = tid; i < ROWS * 16; i += NTHREADS) {  // 5 iters exact
        int r = i >> 4;
        int c4 = i & 15;
        int gr = base + ((r < nrows) ? r : 0);
        cpa16z(&Xs[r * XP + 64 + (c4 << 2)], R + (size_t)gr * 64 + (c4 << 2),
               (r < nrows) ? 16 : 0);
    }
}

// GEMM over K=128; fragment = RPT rows x TC cols per thread, packed f32x2 FMAs.
// TC=8: split column groups (tx*4 and 64+tx*4) -> conflict-free LDS.128.
template <int TC>
__device__ __forceinline__ void gemm128(const float* __restrict__ Xs,
                                        const float* __restrict__ Ws,
                                        int r0, int tx, ull (&acc)[RPT][TC / 2]) {
#pragma unroll
    for (int i = 0; i < RPT; i++)
#pragma unroll
        for (int j = 0; j < TC / 2; j++) acc[i][j] = 0ULL;

#pragma unroll 2
    for (int k = 0; k < 128; k += 4) {
        float4 a[RPT];
#pragma unroll
        for (int i = 0; i < RPT; i++) a[i] = *(const float4*)&Xs[(r0 + i) * XP + k];
#pragma unroll
        for (int kk = 0; kk < 4; kk++) {
            ull b[TC / 2];
            if constexpr (TC == 8) {
                const float* bpa = &Ws[(k + kk) * WPP + tx * 4];
                const float* bpb = &Ws[(k + kk) * WPP + 64 + tx * 4];
                ulonglong2 q0 = *(const ulonglong2*)bpa;
                ulonglong2 q1 = *(const ulonglong2*)bpb;
                b[0] = q0.x; b[1] = q0.y; b[2] = q1.x; b[3] = q1.y;
            } else if constexpr (TC == 4) {
                const float* bp = &Ws[(k + kk) * WPP + tx * 4];
                ulonglong2 q0 = *(const ulonglong2*)bp;
                b[0] = q0.x; b[1] = q0.y;
            } else {
                const float* bp = &Ws[(k + kk) * WPP + tx * 2];
                b[0] = *(const ull*)bp;
            }
#pragma unroll
            for (int i = 0; i < RPT; i++) {
                float av = ((const float*)&a[i])[kk];
                ull ap = pack2(av, av);
#pragma unroll
                for (int j = 0; j < TC / 2; j++) ffma2(acc[i][j], ap, b[j]);
            }
        }
    }
}

// ---------------- kernel B: fused MoE MLP stack (cp.async pipelined) -------
__global__ void __launch_bounds__(NTHREADS, 2)
moe_kernel(const float* __restrict__ cur,
           const float* __restrict__ Wl,  const float* __restrict__ bl,
           const float* __restrict__ Wf1, const float* __restrict__ bf1,
           const float* __restrict__ Wf2, const float* __restrict__ bf2,
           const float* __restrict__ Wc1, const float* __restrict__ bc1,
           const float* __restrict__ Wc2, const float* __restrict__ bc2,
           const float* __restrict__ Wg1, const float* __restrict__ bg1,
           const float* __restrict__ Wg2, const float* __restrict__ bg2,
           float* __restrict__ out, int out_size) {
    extern __shared__ float sm[];
    float* Xs    = sm;                       // [ROWS][XP]
    float* Ws    = Xs + ROWS * XP;           // [128][WPP]  (Gs in cols GSB..GSB+31)
    float* sw    = Ws + 128 * WPP;           // [ROWS][4]
    int*   sflag = (int*)(sw + ROWS * 4);    // [ROWS]

    int tid  = threadIdx.x;
    int base = blockIdx.x * ROWS;
    int nrows = min(ROWS, NCELLS - base);

    int tx = tid & 15;          // 0..15 (column group)
    int ty = tid >> 4;          // 0..15 (row group)
    int r0 = ty * RPT;

    // ================= prologue: gating inputs =================
    fillX_async(Xs, cur, g_act, tid, base, nrows);
    loadW_async<32>(Wg1, Ws, tid);
    if (tid < ROWS)
        sflag[tid] = (base + tid < NCELLS) ? g_flags[base + tid] : 0;
    cp_wait_all();
    __syncthreads();

    // ================= gating =================
    ull ag[RPT][1];
    gemm128<2>(Xs, Ws, r0, tx, ag);
    __syncthreads();           // all Xs/Ws reads done

    // prefetch local-expert data while writing Gs + reducing
    fillXright_async(Xs, g_mean_l, tid, base, nrows);   // Xs cols 64..127
    loadW_async<64>(Wl, Ws, tid);                       // Ws cols 0..63
    {
        float2 bg = *(const float2*)&bg1[tx * 2];
#pragma unroll
        for (int i = 0; i < RPT; i++) {
            int row = r0 + i;
            float2 v = unpack2(ag[i][0]);
            int k0 = tx * 2;
            Ws[row * WPP + GSB + ((k0 + row) & 31)]     = fast_tanh(v.x + bg.x);
            Ws[row * WPP + GSB + ((k0 + 1 + row) & 31)] = fast_tanh(v.y + bg.y);
        }
    }
    __syncthreads();
    if (tid < ROWS) {
        int row = tid;
        float l0 = bg2[0], l1 = bg2[1], l2 = bg2[2];
#pragma unroll
        for (int k = 0; k < 32; k++) {
            float gv = Ws[row * WPP + GSB + ((k + row) & 31)];
            l0 += gv * Wg2[k * 3 + 0];
            l1 += gv * Wg2[k * 3 + 1];
            l2 += gv * Wg2[k * 3 + 2];
        }
        float m = fmaxf(l0, fmaxf(l1, l2));
        float e0 = expf(l0 - m), e1 = expf(l1 - m), e2 = expf(l2 - m);
        float inv = 1.0f / (e0 + e1 + e2);
        float w0 = e0 * inv, w1 = e1 * inv, w2 = e2 * inv;
        sw[row * 4 + 0] = w0; sw[row * 4 + 1] = w1; sw[row * 4 + 2] = w2;
        int gr = base + row;
        if (gr < NCELLS && out_size >= NCELLS * 67) {
            out[(size_t)NCELLS * 64 + (size_t)gr * 3 + 0] = w0;
            out[(size_t)NCELLS * 64 + (size_t)gr * 3 + 1] = w1;
            out[(size_t)NCELLS * 64 + (size_t)gr * 3 + 2] = w2;
        }
    }
    cp_wait_all();
    __syncthreads();

    float2 comb[RPT][2];

    // ================= local expert =================
    {
        ull al[RPT][2];
        gemm128<4>(Xs, Ws, r0, tx, al);
        __syncthreads();       // Xs/Ws reads done
        // prefetch functional-expert data during epilogue
        fillXright_async(Xs, g_mean_f, tid, base, nrows);
        loadW_async<128>(Wf1, Ws, tid);
        float2 b0 = *(const float2*)&bl[tx * 4];
        float2 b1 = *(const float2*)&bl[tx * 4 + 2];
#pragma unroll
        for (int i = 0; i < RPT; i++) {
            int row = r0 + i;
            float w0 = sw[row * 4 + 0];
            bool on = (sflag[row] & 1);
            float2 v0 = unpack2(al[i][0]);
            float2 v1 = unpack2(al[i][1]);
            comb[i][0].x = on ? w0 * fast_tanh(v0.x + b0.x) : 0.f;
            comb[i][0].y = on ? w0 * fast_tanh(v0.y + b0.y) : 0.f;
            comb[i][1].x = on ? w0 * fast_tanh(v1.x + b1.x) : 0.f;
            comb[i][1].y = on ? w0 * fast_tanh(v1.y + b1.y) : 0.f;
        }
        cp_wait_all();
        __syncthreads();
    }

    // ================= functional expert =================
    {
        ull ah[RPT][4];
        gemm128<8>(Xs, Ws, r0, tx, ah);
        __syncthreads();       // all threads done reading Xs/Ws
        loadW_async<64>(Wf2, Ws, tid);   // overlaps tanh(h) epilogue
        float4 b0 = *(const float4*)&bf1[tx * 4];
        float4 b1 = *(const float4*)&bf1[64 + tx * 4];
#pragma unroll
        for (int i = 0; i < RPT; i++) {
            float2 v0 = unpack2(ah[i][0]), v1 = unpack2(ah[i][1]);
            float2 v2 = unpack2(ah[i][2]), v3 = unpack2(ah[i][3]);
            float4 o0 = make_float4(fast_tanh(v0.x + b0.x), fast_tanh(v0.y + b0.y),
                                    fast_tanh(v1.x + b0.z), fast_tanh(v1.y + b0.w));
            float4 o1 = make_float4(fast_tanh(v2.x + b1.x), fast_tanh(v2.y + b1.y),
                                    fast_tanh(v3.x + b1.z), fast_tanh(v3.y + b1.w));
            *(float4*)&Xs[(r0 + i) * XP + tx * 4]      = o0;
            *(float4*)&Xs[(r0 + i) * XP + 64 + tx * 4] = o1;
        }
        cp_wait_all();
        __syncthreads();
    }
    float2 x[RPT][2];
    {
        ull af[RPT][2];
        gemm128<4>(Xs, Ws, r0, tx, af);
        __syncthreads();       // Xs/Ws reads done
        // prefetch CNF step-0 data during epilogue
        loadW_async<128>(Wc1, Ws, tid);
        fillXright_async(Xs, g_mean_d, tid, base, nrows);
        float2 c0 = *(const float2*)&bf2[tx * 4];
        float2 c1 = *(const float2*)&bf2[tx * 4 + 2];
#pragma unroll
        for (int i = 0; i < RPT; i++) {
            int row = r0 + i;
            float w1 = sw[row * 4 + 1];
            bool on = (sflag[row] & 2);
            float2 v0 = unpack2(af[i][0]);
            float2 v1 = unpack2(af[i][1]);
            comb[i][0].x += on ? w1 * fast_tanh(v0.x + c0.x) : 0.f;
            comb[i][0].y += on ? w1 * fast_tanh(v0.y + c0.y) : 0.f;
            comb[i][1].x += on ? w1 * fast_tanh(v1.x + c1.x) : 0.f;
            comb[i][1].y += on ? w1 * fast_tanh(v1.y + c1.y) : 0.f;
            // park comb in OUT (each thread owns out[gr*64 + tx*4 .. +3]) to
            // free registers across the CNF section; re-read + finalize at end
            int gr = base + row;
            if (gr < NCELLS)
                *(float4*)&out[(size_t)gr * 64 + tx * 4] =
                    make_float4(comb[i][0].x, comb[i][0].y, comb[i][1].x, comb[i][1].y);
        }
        // CNF x init (plain LDG, overlaps copies) + stage x into Xs left half
#pragma unroll
        for (int i = 0; i < RPT; i++) {
            int gr = base + r0 + i;
            float4 cv = make_float4(0.f, 0.f, 0.f, 0.f);
            if (gr < NCELLS) cv = *(const float4*)(cur + (size_t)gr * 64 + tx * 4);
            x[i][0] = make_float2(cv.x, cv.y);
            x[i][1] = make_float2(cv.z, cv.w);
            *(float4*)&Xs[(r0 + i) * XP + tx * 4] = cv;
        }
        cp_wait_all();
        __syncthreads();
    }

    // ================= distant expert (CNF, 3 Euler steps) =================
    // loop invariant at top: Xs = [x | mean_d] valid, Ws = Wc1 valid, synced
    const float DT = 1.0f / 3.0f;
    for (int step = 0; step < 3; step++) {
        ull av[RPT][4];
        gemm128<8>(Xs, Ws, r0, tx, av);
        __syncthreads();
        loadW_async<64>(Wc2, Ws, tid);   // overlaps tanh(v) epilogue
        {
            float4 b0 = *(const float4*)&bc1[tx * 4];
            float4 b1 = *(const float4*)&bc1[64 + tx * 4];
#pragma unroll
            for (int i = 0; i < RPT; i++) {
                float2 v0 = unpack2(av[i][0]), v1 = unpack2(av[i][1]);
                float2 v2 = unpack2(av[i][2]), v3 = unpack2(av[i][3]);
                float4 o0 = make_float4(fast_tanh(v0.x + b0.x), fast_tanh(v0.y + b0.y),
                                        fast_tanh(v1.x + b0.z), fast_tanh(v1.y + b0.w));
                float4 o1 = make_float4(fast_tanh(v2.x + b1.x), fast_tanh(v2.y + b1.y),
                                        fast_tanh(v3.x + b1.z), fast_tanh(v3.y + b1.w));
                *(float4*)&Xs[(r0 + i) * XP + tx * 4]      = o0;
                *(float4*)&Xs[(r0 + i) * XP + 64 + tx * 4] = o1;
            }
        }
        cp_wait_all();
        __syncthreads();
        ull ad[RPT][2];
        gemm128<4>(Xs, Ws, r0, tx, ad);
        __syncthreads();
        if (step < 2) {
            loadW_async<128>(Wc1, Ws, tid);            // next step's weights
            fillXright_async(Xs, g_mean_d, tid, base, nrows);  // restore mean_d
        }
        {
            float2 c0 = *(const float2*)&bc2[tx * 4];
            float2 c1 = *(const float2*)&bc2[tx * 4 + 2];
#pragma unroll
            for (int i = 0; i < RPT; i++) {
                float2 v0 = unpack2(ad[i][0]);
                float2 v1 = unpack2(ad[i][1]);
                x[i][0].x += DT * fast_tanh(v0.x + c0.x);
                x[i][0].y += DT * fast_tanh(v0.y + c0.y);
                x[i][1].x += DT * fast_tanh(v1.x + c1.x);
                x[i][1].y += DT * fast_tanh(v1.y + c1.y);
            }
        }
        if (step < 2) {
            // stage updated x into Xs left half for next step
#pragma unroll
            for (int i = 0; i < RPT; i++) {
                float4 xv = make_float4(x[i][0].x, x[i][0].y, x[i][1].x, x[i][1].y);
                *(float4*)&Xs[(r0 + i) * XP + tx * 4] = xv;
            }
            cp_wait_all();
            __syncthreads();
        }
    }

    // ================= unpark comb from out, add CNF term, store ===========
#pragma unroll
    for (int i = 0; i < RPT; i++) {
        int row = r0 + i;
        float w2 = sw[row * 4 + 2];
        bool on = (sflag[row] & 4);
        int gr = base + row;
        if (gr < NCELLS) {
            float4 cb = *(const float4*)&out[(size_t)gr * 64 + tx * 4];  // own cells
            cb.x += on ? w2 * x[i][0].x : 0.f;
            cb.y += on ? w2 * x[i][0].y : 0.f;
            cb.z += on ? w2 * x[i][1].x : 0.f;
            cb.w += on ? w2 * x[i][1].y : 0.f;
            *(float4*)&out[(size_t)gr * 64 + tx * 4] = cb;
        }
    }
}

// ---------------- launch ----------------
extern "C" void kernel_launch(void* const* d_in, const int* in_sizes, int n_in,
                              void* d_out, int out_size) {
    const float* cur = (const float*)d_in[0];
    const float* nb  = (const float*)d_in[1];
    const int*   cat = (const int*)d_in[2];
    const float* Wl  = (const float*)d_in[3];
    const float* bl  = (const float*)d_in[4];
    const float* Wf1 = (const float*)d_in[5];
    const float* bf1 = (const float*)d_in[6];
    const float* Wf2 = (const float*)d_in[7];
    const float* bf2 = (const float*)d_in[8];
    const float* Wc1 = (const float*)d_in[9];
    const float* bc1 = (const float*)d_in[10];
    const float* Wc2 = (const float*)d_in[11];
    const float* bc2 = (const float*)d_in[12];
    const float* Wg1 = (const float*)d_in[13];
    const float* bg1 = (const float*)d_in[14];
    const float* Wg2 = (const float*)d_in[15];
    const float* bg2 = (const float*)d_in[16];
    float* out = (float*)d_out;

    const int smem_bytes = (ROWS * XP + 128 * WPP + ROWS * 4 + ROWS) * 4;
    cudaFuncSetAttribute(moe_kernel, cudaFuncAttributeMaxDynamicSharedMemorySize,
                         smem_bytes);

    int agg_blocks = (NCELLS * 32 + 255) / 256;
    agg_kernel<<<agg_blocks, 256>>>(nb, cat);

    int moe_blocks = (NCELLS + ROWS - 1) / ROWS;   // 247 -> single wave at 2 CTA/SM
    moe_kernel<<<moe_blocks, NTHREADS, smem_bytes>>>(
        cur, Wl, bl, Wf1, bf1, Wf2, bf2, Wc1, bc1, Wc2, bc2,
        Wg1, bg1, Wg2, bg2, out, out_size);
}

// round 15
// speedup vs baseline: 1.5528x; 1.4349x over previous
#include <cuda_runtime.h>
#include <cuda_bf16.h>

#define NCELLS   19683
#define KNB      26
#define ROWS     80    // rows per CTA tile -> grid 247 (single wave @ 2 CTA/SM)
#define NTHREADS 256
#define PKX      68    // Xs plane row pitch (32-bit words; 64 data + 4 pad)
#define PKW      68    // Ws plane row pitch (words; 64 data + 4 pad; mult-of-4 for cp.async 16B)

// smem word offsets
#define OXH 0
#define OXL 5440          // 80*68
#define OWH 10880
#define OWL 19584         // 10880 + 128*68
#define SMW_TOTAL 28288   // 19584 + 128*68 -> 113,152 bytes

// weight-plane word offsets in global scratch
#define WOG1 0
#define WOL  2048
#define WOF1 6144
#define WOF2 14336
#define WOC1 18432
#define WOC2 26624
#define WTOT 30720

#define CURW (19683 * 32)

// ---------------- global scratch (allocation-free) ----------------
__device__ unsigned g_curH[CURW], g_curL[CURW];
__device__ unsigned g_mlH[CURW],  g_mlL[CURW];
__device__ unsigned g_mfH[CURW],  g_mfL[CURW];
__device__ unsigned g_mdH[CURW],  g_mdL[CURW];
__device__ unsigned g_acH[CURW],  g_acL[CURW];
__device__ unsigned g_wH[WTOT],   g_wL[WTOT];
__device__ int      g_flags[NCELLS];

// ---------------- helpers ----------------
__device__ __forceinline__ float fast_tanh(float x) {
    float ax = fabsf(x);
    float t  = __expf(-2.0f * ax);
    float r  = __fdividef(1.0f - t, 1.0f + t);
    return copysignf(r, x);
}

// split (x0,x1) -> packed bf16x2 hi word (return) + lo word (out param)
__device__ __forceinline__ unsigned bsplit(float x0, float x1, unsigned& lo) {
    __nv_bfloat16 h0 = __float2bfloat16(x0), h1 = __float2bfloat16(x1);
    float r0 = x0 - __bfloat162float(h0);
    float r1 = x1 - __bfloat162float(h1);
    __nv_bfloat16 l0 = __float2bfloat16(r0), l1 = __float2bfloat16(r1);
    lo = (unsigned)__bfloat16_as_ushort(l0) | ((unsigned)__bfloat16_as_ushort(l1) << 16);
    return (unsigned)__bfloat16_as_ushort(h0) | ((unsigned)__bfloat16_as_ushort(h1) << 16);
}

__device__ __forceinline__ void mma4(float (&c)[4], unsigned a0, unsigned a1,
                                     unsigned a2, unsigned a3, unsigned b0, unsigned b1) {
    asm("mma.sync.aligned.m16n8k16.row.col.f32.bf16.bf16.f32 "
        "{%0,%1,%2,%3},{%4,%5,%6,%7},{%8,%9},{%0,%1,%2,%3};"
        : "+f"(c[0]), "+f"(c[1]), "+f"(c[2]), "+f"(c[3])
        : "r"(a0), "r"(a1), "r"(a2), "r"(a3), "r"(b0), "r"(b1));
}

__device__ __forceinline__ void cpa16(void* s, const void* g) {
    unsigned sa = (unsigned)__cvta_generic_to_shared(s);
    asm volatile("cp.async.ca.shared.global [%0], [%1], 16;" :: "r"(sa), "l"(g));
}
__device__ __forceinline__ void cp_wait_all() {
    asm volatile("cp.async.wait_all;" ::: "memory");
}

// ---------------- prep kernel: split cur + weights into bf16 planes --------
__global__ void prep_kernel(const float* __restrict__ cur,
                            const float* __restrict__ Wg1, const float* __restrict__ Wl,
                            const float* __restrict__ Wf1, const float* __restrict__ Wf2,
                            const float* __restrict__ Wc1, const float* __restrict__ Wc2) {
    int idx = blockIdx.x * blockDim.x + threadIdx.x;
    if (idx < CURW) {
        int k2 = idx & 31; int row = idx >> 5;
        float2 v = *(const float2*)(cur + (size_t)row * 64 + k2 * 2);
        unsigned lo, hi = bsplit(v.x, v.y, lo);
        g_curH[idx] = hi; g_curL[idx] = lo;
        return;
    }
    int j = idx - CURW;
    const float* W; int NC; int off;
    if (j < 2048)              { W = Wg1; NC = 32;  off = WOG1; }
    else if ((j -= 2048) < 4096) { W = Wl;  NC = 64;  off = WOL;  }
    else if ((j -= 4096) < 8192) { W = Wf1; NC = 128; off = WOF1; }
    else if ((j -= 8192) < 4096) { W = Wf2; NC = 64;  off = WOF2; }
    else if ((j -= 4096) < 8192) { W = Wc1; NC = 128; off = WOC1; }
    else if ((j -= 8192) < 4096) { W = Wc2; NC = 64;  off = WOC2; }
    else return;
    int k2 = j / NC; int n = j - k2 * NC;
    float w0 = W[(2 * k2) * NC + n];
    float w1 = W[(2 * k2 + 1) * NC + n];
    unsigned lo, hi = bsplit(w0, w1, lo);
    g_wH[off + n * 64 + k2] = hi;   // transposed: row n holds contiguous k
    g_wL[off + n * 64 + k2] = lo;
}

// ---------------- agg kernel: masked means -> bf16 planes ------------------
__global__ void agg_kernel(const float* __restrict__ nb, const int* __restrict__ cat) {
    int gw = (blockIdx.x * blockDim.x + threadIdx.x) >> 5;
    if (gw >= NCELLS) return;
    int lane = threadIdx.x & 31;
    const float* base = nb + (size_t)gw * (KNB * 64);
    int myc = (lane < KNB) ? cat[gw * KNB + lane] : -1;

    unsigned m0 = __ballot_sync(0xffffffffu, myc == 0);
    unsigned m1 = __ballot_sync(0xffffffffu, myc == 1);
    unsigned m2 = __ballot_sync(0xffffffffu, myc == 2);

    float2 s0 = {0.f, 0.f}, s1 = {0.f, 0.f}, s2 = {0.f, 0.f}, sa = {0.f, 0.f};
#pragma unroll
    for (int k = 0; k < KNB; k++) {
        float2 v = *(const float2*)(base + k * 64 + lane * 2);
        sa.x += v.x; sa.y += v.y;
        bool b0 = (m0 >> k) & 1u;
        bool b1 = (m1 >> k) & 1u;
        bool b2 = (m2 >> k) & 1u;
        s0.x += b0 ? v.x : 0.f;  s0.y += b0 ? v.y : 0.f;
        s1.x += b1 ? v.x : 0.f;  s1.y += b1 ? v.y : 0.f;
        s2.x += b2 ? v.x : 0.f;  s2.y += b2 ? v.y : 0.f;
    }
    int c0 = __popc(m0), c1 = __popc(m1), c2 = __popc(m2);
    float d0 = fmaxf((float)c0, 1.0f);
    float d1 = fmaxf((float)c1, 1.0f);
    float d2 = fmaxf((float)c2, 1.0f);
    int off = gw * 32 + lane;
    unsigned lo, hi;
    hi = bsplit(s0.x / d0, s0.y / d0, lo);      g_mlH[off] = hi; g_mlL[off] = lo;
    hi = bsplit(s1.x / d1, s1.y / d1, lo);      g_mfH[off] = hi; g_mfL[off] = lo;
    hi = bsplit(s2.x / d2, s2.y / d2, lo);      g_mdH[off] = hi; g_mdL[off] = lo;
    hi = bsplit(sa.x / 26.0f, sa.y / 26.0f, lo); g_acH[off] = hi; g_acL[off] = lo;
    if (lane == 0)
        g_flags[gw] = (c0 > 0 ? 1 : 0) | (c1 > 0 ? 2 : 0) | (c2 > 0 ? 4 : 0);
}

// ---------------- moe helpers ----------------
__device__ __forceinline__ void fillLeft(unsigned* smw, int tid, int base, int nrows) {
    for (int i = tid; i < ROWS * 8; i += NTHREADS) {
        int r = i >> 3, c = i & 7;
        int gr = base + ((r < nrows) ? r : 0);
        cpa16(smw + OXH + r * PKX + c * 4, g_curH + (size_t)gr * 32 + c * 4);
        cpa16(smw + OXL + r * PKX + c * 4, g_curL + (size_t)gr * 32 + c * 4);
    }
}
__device__ __forceinline__ void fillRight(unsigned* smw, const unsigned* __restrict__ srcH,
                                          const unsigned* __restrict__ srcL,
                                          int tid, int base, int nrows) {
    for (int i = tid; i < ROWS * 8; i += NTHREADS) {
        int r = i >> 3, c = i & 7;
        int gr = base + ((r < nrows) ? r : 0);
        cpa16(smw + OXH + r * PKX + 32 + c * 4, srcH + (size_t)gr * 32 + c * 4);
        cpa16(smw + OXL + r * PKX + 32 + c * 4, srcL + (size_t)gr * 32 + c * 4);
    }
}
template <int NC>
__device__ __forceinline__ void loadWp(unsigned* smw, int off, int tid) {
    for (int i = tid; i < NC * 16; i += NTHREADS) {
        int r = i >> 4, c = i & 15;
        cpa16(smw + OWH + r * PKW + c * 4, g_wH + off + r * 64 + c * 4);
        cpa16(smw + OWL + r * PKW + c * 4, g_wL + off + r * 64 + c * 4);
    }
}

// split-precision MMA GEMM: 80 x (NT*8 per warp) x 128, acc fp32 fragments
template <int NT>
__device__ __forceinline__ void mma_gemm(const unsigned* __restrict__ smw,
                                         int nt0, int g, int tig, float (&acc)[5][NT][4]) {
#pragma unroll
    for (int mt = 0; mt < 5; mt++)
#pragma unroll
        for (int j = 0; j < NT; j++)
#pragma unroll
            for (int k = 0; k < 4; k++) acc[mt][j][k] = 0.f;

    const unsigned* XH = smw + OXH;
    const unsigned* XL = smw + OXL;
    const unsigned* WH = smw + OWH;
    const unsigned* WL = smw + OWL;
#pragma unroll
    for (int ks = 0; ks < 8; ks++) {
        unsigned bh[NT][2], blo[NT][2];
#pragma unroll
        for (int j = 0; j < NT; j++) {
            int wr = ((nt0 + j) * 8 + g) * PKW + ks * 8 + tig;
            bh[j][0] = WH[wr]; bh[j][1] = WH[wr + 4];
            blo[j][0] = WL[wr]; blo[j][1] = WL[wr + 4];
        }
#pragma unroll
        for (int mt = 0; mt < 5; mt++) {
            int xr = (mt * 16 + g) * PKX + ks * 8 + tig;
            unsigned a0 = XH[xr], a1 = XH[xr + 8 * PKX], a2 = XH[xr + 4], a3 = XH[xr + 8 * PKX + 4];
            unsigned l0 = XL[xr], l1 = XL[xr + 8 * PKX], l2 = XL[xr + 4], l3 = XL[xr + 8 * PKX + 4];
#pragma unroll
            for (int j = 0; j < NT; j++) {
                mma4(acc[mt][j], a0, a1, a2, a3, bh[j][0], bh[j][1]);
                mma4(acc[mt][j], a0, a1, a2, a3, blo[j][0], blo[j][1]);
                mma4(acc[mt][j], l0, l1, l2, l3, bh[j][0], bh[j][1]);
            }
        }
    }
}

// ---------------- moe kernel ----------------
__global__ void __launch_bounds__(NTHREADS, 2)
moe_kernel(const float* __restrict__ cur,
           const float* __restrict__ bl,  const float* __restrict__ bf1,
           const float* __restrict__ bf2, const float* __restrict__ bc1,
           const float* __restrict__ bc2, const float* __restrict__ bg1,
           const float* __restrict__ Wg2, const float* __restrict__ bg2,
           float* __restrict__ out, int out_size) {
    extern __shared__ unsigned smw[];
    float* smf = (float*)smw;
    int*   smi = (int*)smw;

    int tid = threadIdx.x;
    int warp = tid >> 5, lane = tid & 31;
    int g = lane >> 2, tig = lane & 3;
    int base = blockIdx.x * ROWS;
    int nrows = min(ROWS, NCELLS - base);
    int col0 = warp * 8 + tig * 2;

    // ============ prologue: [cur | act] planes + Wg1 planes + flags ========
    fillLeft(smw, tid, base, nrows);
    fillRight(smw, g_acH, g_acL, tid, base, nrows);
    loadWp<32>(smw, WOG1, tid);
    if (tid < ROWS)
        smi[tid * PKX + 67] = (base + tid < NCELLS) ? g_flags[base + tid] : 0;   // sflag in Xs pad
    cp_wait_all();
    __syncthreads();

    // ============ gating ============
    {
        float accg[5][1][4];
        if (warp < 4) mma_gemm<1>(smw, warp, g, tig, accg);
        __syncthreads();                 // plane reads done
        fillRight(smw, g_mlH, g_mlL, tid, base, nrows);   // prefetch mean_l
        if (warp < 4) {
            float* Gsf = (float*)(smw + OWH);   // overlay, pitch 33
            int c = warp * 8 + tig * 2;
            float b0 = bg1[c], b1 = bg1[c + 1];
#pragma unroll
            for (int mt = 0; mt < 5; mt++) {
                int r0 = mt * 16 + g, r1 = r0 + 8;
                Gsf[r0 * 33 + c]     = fast_tanh(accg[mt][0][0] + b0);
                Gsf[r0 * 33 + c + 1] = fast_tanh(accg[mt][0][1] + b1);
                Gsf[r1 * 33 + c]     = fast_tanh(accg[mt][0][2] + b0);
                Gsf[r1 * 33 + c + 1] = fast_tanh(accg[mt][0][3] + b1);
            }
        }
        __syncthreads();
        if (tid < ROWS) {
            const float* Gsf = (const float*)(smw + OWH);
            float l0 = bg2[0], l1 = bg2[1], l2 = bg2[2];
#pragma unroll
            for (int k = 0; k < 32; k++) {
                float gv = Gsf[tid * 33 + k];
                l0 += gv * Wg2[k * 3 + 0];
                l1 += gv * Wg2[k * 3 + 1];
                l2 += gv * Wg2[k * 3 + 2];
            }
            float m = fmaxf(l0, fmaxf(l1, l2));
            float e0 = expf(l0 - m), e1 = expf(l1 - m), e2 = expf(l2 - m);
            float inv = 1.0f / (e0 + e1 + e2);
            float w0 = e0 * inv, w1 = e1 * inv, w2 = e2 * inv;
            smf[tid * PKX + 64] = w0;   // sw in Xs pad
            smf[tid * PKX + 65] = w1;
            smf[tid * PKX + 66] = w2;
            int gr = base + tid;
            if (gr < NCELLS && out_size >= NCELLS * 67) {
                out[(size_t)NCELLS * 64 + (size_t)gr * 3 + 0] = w0;
                out[(size_t)NCELLS * 64 + (size_t)gr * 3 + 1] = w1;
                out[(size_t)NCELLS * 64 + (size_t)gr * 3 + 2] = w2;
            }
        }
        __syncthreads();                 // Gs reads done -> Ws reusable
        loadWp<64>(smw, WOL, tid);
        cp_wait_all();
        __syncthreads();
    }

    float comb[5][4];

    // ============ local expert ============
    {
        float accl[5][1][4];
        mma_gemm<1>(smw, warp, g, tig, accl);
        __syncthreads();
        fillRight(smw, g_mfH, g_mfL, tid, base, nrows);
        loadWp<128>(smw, WOF1, tid);
        float b0v = bl[col0], b1v = bl[col0 + 1];
#pragma unroll
        for (int mt = 0; mt < 5; mt++) {
            int r0 = mt * 16 + g, r1 = r0 + 8;
            float w0a = smf[r0 * PKX + 64]; int f0 = smi[r0 * PKX + 67] & 1;
            float w0b = smf[r1 * PKX + 64]; int f1 = smi[r1 * PKX + 67] & 1;
            comb[mt][0] = f0 ? w0a * fast_tanh(accl[mt][0][0] + b0v) : 0.f;
            comb[mt][1] = f0 ? w0a * fast_tanh(accl[mt][0][1] + b1v) : 0.f;
            comb[mt][2] = f1 ? w0b * fast_tanh(accl[mt][0][2] + b0v) : 0.f;
            comb[mt][3] = f1 ? w0b * fast_tanh(accl[mt][0][3] + b1v) : 0.f;
        }
        cp_wait_all();
        __syncthreads();
    }

    // ============ functional expert L1 ============
    {
        float acch[5][2][4];
        mma_gemm<2>(smw, warp * 2, g, tig, acch);
        __syncthreads();
        loadWp<64>(smw, WOF2, tid);
#pragma unroll
        for (int j = 0; j < 2; j++) {
            int cj = (warp * 2 + j) * 8 + tig * 2;
            float bj0 = bf1[cj], bj1 = bf1[cj + 1];
            int wc = (cj >> 1);
#pragma unroll
            for (int mt = 0; mt < 5; mt++) {
                int r0 = mt * 16 + g, r1 = r0 + 8;
                float t0 = fast_tanh(acch[mt][j][0] + bj0);
                float t1 = fast_tanh(acch[mt][j][1] + bj1);
                float t2 = fast_tanh(acch[mt][j][2] + bj0);
                float t3 = fast_tanh(acch[mt][j][3] + bj1);
                unsigned lo, hi;
                hi = bsplit(t0, t1, lo);
                smw[OXH + r0 * PKX + wc] = hi; smw[OXL + r0 * PKX + wc] = lo;
                hi = bsplit(t2, t3, lo);
                smw[OXH + r1 * PKX + wc] = hi; smw[OXL + r1 * PKX + wc] = lo;
            }
        }
        cp_wait_all();
        __syncthreads();
    }

    // ============ functional expert L2 + CNF setup ============
    float x[5][4];
    {
        float accf[5][1][4];
        mma_gemm<1>(smw, warp, g, tig, accf);
        __syncthreads();
        fillRight(smw, g_mdH, g_mdL, tid, base, nrows);
        loadWp<128>(smw, WOC1, tid);
        float c0v = bf2[col0], c1v = bf2[col0 + 1];
#pragma unroll
        for (int mt = 0; mt < 5; mt++) {
            int r0 = mt * 16 + g, r1 = r0 + 8;
            float w1a = smf[r0 * PKX + 65]; int f0 = smi[r0 * PKX + 67] & 2;
            float w1b = smf[r1 * PKX + 65]; int f1 = smi[r1 * PKX + 67] & 2;
            comb[mt][0] += f0 ? w1a * fast_tanh(accf[mt][0][0] + c0v) : 0.f;
            comb[mt][1] += f0 ? w1a * fast_tanh(accf[mt][0][1] + c1v) : 0.f;
            comb[mt][2] += f1 ? w1b * fast_tanh(accf[mt][0][2] + c0v) : 0.f;
            comb[mt][3] += f1 ? w1b * fast_tanh(accf[mt][0][3] + c1v) : 0.f;
            // park comb in out (each thread owns these cells exclusively)
            int gr0 = base + r0, gr1 = base + r1;
            if (gr0 < NCELLS)
                *(float2*)&out[(size_t)gr0 * 64 + col0] = make_float2(comb[mt][0], comb[mt][1]);
            if (gr1 < NCELLS)
                *(float2*)&out[(size_t)gr1 * 64 + col0] = make_float2(comb[mt][2], comb[mt][3]);
        }
        // CNF x init + stage into Xs left half
        int wcl = warp * 4 + tig;
#pragma unroll
        for (int mt = 0; mt < 5; mt++) {
            int r0 = mt * 16 + g, r1 = r0 + 8;
            int gr0 = base + r0, gr1 = base + r1;
            float2 v0 = (gr0 < NCELLS) ? *(const float2*)(cur + (size_t)gr0 * 64 + col0)
                                       : make_float2(0.f, 0.f);
            float2 v1 = (gr1 < NCELLS) ? *(const float2*)(cur + (size_t)gr1 * 64 + col0)
                                       : make_float2(0.f, 0.f);
            x[mt][0] = v0.x; x[mt][1] = v0.y; x[mt][2] = v1.x; x[mt][3] = v1.y;
            unsigned lo, hi;
            hi = bsplit(v0.x, v0.y, lo);
            smw[OXH + r0 * PKX + wcl] = hi; smw[OXL + r0 * PKX + wcl] = lo;
            hi = bsplit(v1.x, v1.y, lo);
            smw[OXH + r1 * PKX + wcl] = hi; smw[OXL + r1 * PKX + wcl] = lo;
        }
        cp_wait_all();
        __syncthreads();
    }

    // ============ distant expert: CNF 3 Euler steps ============
    const float DT = 1.0f / 3.0f;
    for (int step = 0; step < 3; step++) {
        {
            float accv[5][2][4];
            mma_gemm<2>(smw, warp * 2, g, tig, accv);
            __syncthreads();
            loadWp<64>(smw, WOC2, tid);
#pragma unroll
            for (int j = 0; j < 2; j++) {
                int cj = (warp * 2 + j) * 8 + tig * 2;
                float bj0 = bc1[cj], bj1 = bc1[cj + 1];
                int wc = (cj >> 1);
#pragma unroll
                for (int mt = 0; mt < 5; mt++) {
                    int r0 = mt * 16 + g, r1 = r0 + 8;
                    float t0 = fast_tanh(accv[mt][j][0] + bj0);
                    float t1 = fast_tanh(accv[mt][j][1] + bj1);
                    float t2 = fast_tanh(accv[mt][j][2] + bj0);
                    float t3 = fast_tanh(accv[mt][j][3] + bj1);
                    unsigned lo, hi;
                    hi = bsplit(t0, t1, lo);
                    smw[OXH + r0 * PKX + wc] = hi; smw[OXL + r0 * PKX + wc] = lo;
                    hi = bsplit(t2, t3, lo);
                    smw[OXH + r1 * PKX + wc] = hi; smw[OXL + r1 * PKX + wc] = lo;
                }
            }
            cp_wait_all();
            __syncthreads();
        }
        {
            float accd[5][1][4];
            mma_gemm<1>(smw, warp, g, tig, accd);
            __syncthreads();
            if (step < 2) {
                loadWp<128>(smw, WOC1, tid);
                fillRight(smw, g_mdH, g_mdL, tid, base, nrows);
            }
            float bb0 = bc2[col0], bb1 = bc2[col0 + 1];
#pragma unroll
            for (int mt = 0; mt < 5; mt++) {
                x[mt][0] += DT * fast_tanh(accd[mt][0][0] + bb0);
                x[mt][1] += DT * fast_tanh(accd[mt][0][1] + bb1);
                x[mt][2] += DT * fast_tanh(accd[mt][0][2] + bb0);
                x[mt][3] += DT * fast_tanh(accd[mt][0][3] + bb1);
            }
            if (step < 2) {
                int wcl = warp * 4 + tig;
#pragma unroll
                for (int mt = 0; mt < 5; mt++) {
                    int r0 = mt * 16 + g, r1 = r0 + 8;
                    unsigned lo, hi;
                    hi = bsplit(x[mt][0], x[mt][1], lo);
                    smw[OXH + r0 * PKX + wcl] = hi; smw[OXL + r0 * PKX + wcl] = lo;
                    hi = bsplit(x[mt][2], x[mt][3], lo);
                    smw[OXH + r1 * PKX + wcl] = hi; smw[OXL + r1 * PKX + wcl] = lo;
                }
                cp_wait_all();
                __syncthreads();
            }
        }
    }

    // ============ unpark comb, add CNF term, store ============
#pragma unroll
    for (int mt = 0; mt < 5; mt++) {
        int r0 = mt * 16 + g, r1 = r0 + 8;
        float w2a = smf[r0 * PKX + 66]; int f0 = smi[r0 * PKX + 67] & 4;
        float w2b = smf[r1 * PKX + 66]; int f1 = smi[r1 * PKX + 67] & 4;
        int gr0 = base + r0, gr1 = base + r1;
        if (gr0 < NCELLS) {
            float2 o = *(const float2*)&out[(size_t)gr0 * 64 + col0];
            o.x += f0 ? w2a * x[mt][0] : 0.f;
            o.y += f0 ? w2a * x[mt][1] : 0.f;
            *(float2*)&out[(size_t)gr0 * 64 + col0] = o;
        }
        if (gr1 < NCELLS) {
            float2 o = *(const float2*)&out[(size_t)gr1 * 64 + col0];
            o.x += f1 ? w2b * x[mt][2] : 0.f;
            o.y += f1 ? w2b * x[mt][3] : 0.f;
            *(float2*)&out[(size_t)gr1 * 64 + col0] = o;
        }
    }
}

// ---------------- launch ----------------
extern "C" void kernel_launch(void* const* d_in, const int* in_sizes, int n_in,
                              void* d_out, int out_size) {
    const float* cur = (const float*)d_in[0];
    const float* nb  = (const float*)d_in[1];
    const int*   cat = (const int*)d_in[2];
    const float* Wl  = (const float*)d_in[3];
    const float* bl  = (const float*)d_in[4];
    const float* Wf1 = (const float*)d_in[5];
    const float* bf1 = (const float*)d_in[6];
    const float* Wf2 = (const float*)d_in[7];
    const float* bf2 = (const float*)d_in[8];
    const float* Wc1 = (const float*)d_in[9];
    const float* bc1 = (const float*)d_in[10];
    const float* Wc2 = (const float*)d_in[11];
    const float* bc2 = (const float*)d_in[12];
    const float* Wg1 = (const float*)d_in[13];
    const float* bg1 = (const float*)d_in[14];
    const float* Wg2 = (const float*)d_in[15];
    const float* bg2 = (const float*)d_in[16];
    float* out = (float*)d_out;

    const int smem_bytes = SMW_TOTAL * 4;   // 113,152 B
    cudaFuncSetAttribute(moe_kernel, cudaFuncAttributeMaxDynamicSharedMemorySize,
                         smem_bytes);

    int prep_total = CURW + WTOT;
    prep_kernel<<<(prep_total + 255) / 256, 256>>>(cur, Wg1, Wl, Wf1, Wf2, Wc1, Wc2);

    int agg_blocks = (NCELLS * 32 + 255) / 256;
    agg_kernel<<<agg_blocks, 256>>>(nb, cat);

    int moe_blocks = (NCELLS + ROWS - 1) / ROWS;   // 247 -> single wave at 2 CTA/SM
    moe_kernel<<<moe_blocks, NTHREADS, smem_bytes>>>(
        cur, bl, bf1, bf2, bc1, bc2, bg1, Wg2, bg2, out, out_size);
}

// round 16
// speedup vs baseline: 2.0838x; 1.3420x over previous
#include <cuda_runtime.h>
#include <cuda_fp16.h>

#define NCELLS   19683
#define KNB      26
#define ROWS     80    // rows per CTA tile -> grid 247 (single wave @ 2 CTA/SM)
#define NTHREADS 256
#define PKX      68    // Xs row pitch (32-bit words; 64 data + 4 pad: sw+flag)
#define PKW      68    // Ws plane row pitch (words; mult-of-4 for cp.async 16B)

// smem word offsets (fp16: A single plane, B two planes)
#define OXH 0
#define OWH 5440          // 80*68
#define OWL 14144         // 5440 + 128*68
#define SMW_TOTAL 22848   // 14144 + 128*68 -> 91,392 bytes

// weight-plane word offsets in global scratch
#define WOG1 0
#define WOL  2048
#define WOF1 6144
#define WOF2 14336
#define WOC1 18432
#define WOC2 26624
#define WTOT 30720

#define CURW (19683 * 32)
#define PREPB 2581        // prep blocks: ceil((CURW + WTOT)/256)
#define AGGB  2461        // agg blocks:  ceil(NCELLS*32/256)

// ---------------- global scratch (allocation-free) ----------------
__device__ unsigned g_cur[CURW];            // fp16x2, activations single plane
__device__ unsigned g_ml[CURW], g_mf[CURW], g_md[CURW], g_ac[CURW];
__device__ unsigned g_wH[WTOT], g_wL[WTOT]; // weights: fp16 hi + lo planes
__device__ int      g_flags[NCELLS];

// ---------------- helpers ----------------
__device__ __forceinline__ float fast_tanh(float x) {
    float ax = fabsf(x);
    float t  = __expf(-2.0f * ax);
    float r  = __fdividef(1.0f - t, 1.0f + t);
    return copysignf(r, x);
}

__device__ __forceinline__ unsigned fpack(float x0, float x1) {
    __half2 h = __floats2half2_rn(x0, x1);
    return *reinterpret_cast<unsigned*>(&h);
}

// split (x0,x1) -> packed fp16x2 hi (return) + residual lo (out param)
__device__ __forceinline__ unsigned fsplit(float x0, float x1, unsigned& lo) {
    __half h0 = __float2half_rn(x0), h1 = __float2half_rn(x1);
    float r0 = x0 - __half2float(h0);
    float r1 = x1 - __half2float(h1);
    lo = fpack(r0, r1);
    __half2 h; h.x = h0; h.y = h1;
    return *reinterpret_cast<unsigned*>(&h);
}

__device__ __forceinline__ void mma4(float (&c)[4], unsigned a0, unsigned a1,
                                     unsigned a2, unsigned a3, unsigned b0, unsigned b1) {
    asm("mma.sync.aligned.m16n8k16.row.col.f32.f16.f16.f32 "
        "{%0,%1,%2,%3},{%4,%5,%6,%7},{%8,%9},{%0,%1,%2,%3};"
        : "+f"(c[0]), "+f"(c[1]), "+f"(c[2]), "+f"(c[3])
        : "r"(a0), "r"(a1), "r"(a2), "r"(a3), "r"(b0), "r"(b1));
}

__device__ __forceinline__ void cpa16(void* s, const void* g) {
    unsigned sa = (unsigned)__cvta_generic_to_shared(s);
    asm volatile("cp.async.ca.shared.global [%0], [%1], 16;" :: "r"(sa), "l"(g));
}
__device__ __forceinline__ void cp_wait_all() {
    asm volatile("cp.async.wait_all;" ::: "memory");
}

// ---------------- fused pre kernel: prep (blocks < PREPB) + agg ------------
__global__ void pre_kernel(const float* __restrict__ cur,
                           const float* __restrict__ Wg1, const float* __restrict__ Wl,
                           const float* __restrict__ Wf1, const float* __restrict__ Wf2,
                           const float* __restrict__ Wc1, const float* __restrict__ Wc2,
                           const float* __restrict__ nb,  const int* __restrict__ cat) {
    if (blockIdx.x < PREPB) {
        int idx = blockIdx.x * blockDim.x + threadIdx.x;
        if (idx < CURW) {
            int k2 = idx & 31; int row = idx >> 5;
            float2 v = *(const float2*)(cur + (size_t)row * 64 + k2 * 2);
            g_cur[idx] = fpack(v.x, v.y);
            return;
        }
        int j = idx - CURW;
        const float* W; int NC; int off;
        if (j < 2048)                { W = Wg1; NC = 32;  off = WOG1; }
        else if ((j -= 2048) < 4096) { W = Wl;  NC = 64;  off = WOL;  }
        else if ((j -= 4096) < 8192) { W = Wf1; NC = 128; off = WOF1; }
        else if ((j -= 8192) < 4096) { W = Wf2; NC = 64;  off = WOF2; }
        else if ((j -= 4096) < 8192) { W = Wc1; NC = 128; off = WOC1; }
        else if ((j -= 8192) < 4096) { W = Wc2; NC = 64;  off = WOC2; }
        else return;
        int k2 = j / NC; int n = j - k2 * NC;
        float w0 = W[(2 * k2) * NC + n];
        float w1 = W[(2 * k2 + 1) * NC + n];
        unsigned lo, hi = fsplit(w0, w1, lo);
        g_wH[off + n * 64 + k2] = hi;   // transposed: row n holds contiguous k
        g_wL[off + n * 64 + k2] = lo;
        return;
    }
    // ---- agg part ----
    int gw = ((blockIdx.x - PREPB) * blockDim.x + threadIdx.x) >> 5;
    if (gw >= NCELLS) return;
    int lane = threadIdx.x & 31;
    const float* base = nb + (size_t)gw * (KNB * 64);
    int myc = (lane < KNB) ? cat[gw * KNB + lane] : -1;

    unsigned m0 = __ballot_sync(0xffffffffu, myc == 0);
    unsigned m1 = __ballot_sync(0xffffffffu, myc == 1);
    unsigned m2 = __ballot_sync(0xffffffffu, myc == 2);

    float2 s0 = {0.f, 0.f}, s1 = {0.f, 0.f}, s2 = {0.f, 0.f}, sa = {0.f, 0.f};
#pragma unroll
    for (int k = 0; k < KNB; k++) {
        float2 v = *(const float2*)(base + k * 64 + lane * 2);
        sa.x += v.x; sa.y += v.y;
        bool b0 = (m0 >> k) & 1u;
        bool b1 = (m1 >> k) & 1u;
        bool b2 = (m2 >> k) & 1u;
        s0.x += b0 ? v.x : 0.f;  s0.y += b0 ? v.y : 0.f;
        s1.x += b1 ? v.x : 0.f;  s1.y += b1 ? v.y : 0.f;
        s2.x += b2 ? v.x : 0.f;  s2.y += b2 ? v.y : 0.f;
    }
    int c0 = __popc(m0), c1 = __popc(m1), c2 = __popc(m2);
    float d0 = fmaxf((float)c0, 1.0f);
    float d1 = fmaxf((float)c1, 1.0f);
    float d2 = fmaxf((float)c2, 1.0f);
    int off = gw * 32 + lane;
    g_ml[off] = fpack(s0.x / d0, s0.y / d0);
    g_mf[off] = fpack(s1.x / d1, s1.y / d1);
    g_md[off] = fpack(s2.x / d2, s2.y / d2);
    g_ac[off] = fpack(sa.x / 26.0f, sa.y / 26.0f);
    if (lane == 0)
        g_flags[gw] = (c0 > 0 ? 1 : 0) | (c1 > 0 ? 2 : 0) | (c2 > 0 ? 4 : 0);
}

// ---------------- moe helpers ----------------
__device__ __forceinline__ void fillLeft(unsigned* smw, int tid, int base, int nrows) {
    for (int i = tid; i < ROWS * 8; i += NTHREADS) {
        int r = i >> 3, c = i & 7;
        int gr = base + ((r < nrows) ? r : 0);
        cpa16(smw + OXH + r * PKX + c * 4, g_cur + (size_t)gr * 32 + c * 4);
    }
}
__device__ __forceinline__ void fillRight(unsigned* smw, const unsigned* __restrict__ src,
                                          int tid, int base, int nrows) {
    for (int i = tid; i < ROWS * 8; i += NTHREADS) {
        int r = i >> 3, c = i & 7;
        int gr = base + ((r < nrows) ? r : 0);
        cpa16(smw + OXH + r * PKX + 32 + c * 4, src + (size_t)gr * 32 + c * 4);
    }
}
template <int NC>
__device__ __forceinline__ void loadWp(unsigned* smw, int off, int tid) {
    for (int i = tid; i < NC * 16; i += NTHREADS) {
        int r = i >> 4, c = i & 15;
        cpa16(smw + OWH + r * PKW + c * 4, g_wH + off + r * 64 + c * 4);
        cpa16(smw + OWL + r * PKW + c * 4, g_wL + off + r * 64 + c * 4);
    }
}

// fp16 2-MMA split GEMM: 80 x (NT*8 per warp) x 128
// A single plane (hi); B hi+lo planes:  C = A_h*B_h + A_h*B_l  (= A_h * B)
template <int NT>
__device__ __forceinline__ void mma_gemm(const unsigned* __restrict__ smw,
                                         int nt0, int g, int tig, float (&acc)[5][NT][4]) {
#pragma unroll
    for (int mt = 0; mt < 5; mt++)
#pragma unroll
        for (int j = 0; j < NT; j++)
#pragma unroll
            for (int k = 0; k < 4; k++) acc[mt][j][k] = 0.f;

    const unsigned* XH = smw + OXH;
    const unsigned* WH = smw + OWH;
    const unsigned* WL = smw + OWL;
#pragma unroll
    for (int ks = 0; ks < 8; ks++) {
        unsigned bh[NT][2], blo[NT][2];
#pragma unroll
        for (int j = 0; j < NT; j++) {
            int wr = ((nt0 + j) * 8 + g) * PKW + ks * 8 + tig;
            bh[j][0] = WH[wr]; bh[j][1] = WH[wr + 4];
            blo[j][0] = WL[wr]; blo[j][1] = WL[wr + 4];
        }
#pragma unroll
        for (int mt = 0; mt < 5; mt++) {
            int xr = (mt * 16 + g) * PKX + ks * 8 + tig;
            unsigned a0 = XH[xr], a1 = XH[xr + 8 * PKX], a2 = XH[xr + 4], a3 = XH[xr + 8 * PKX + 4];
#pragma unroll
            for (int j = 0; j < NT; j++) {
                mma4(acc[mt][j], a0, a1, a2, a3, bh[j][0], bh[j][1]);
                mma4(acc[mt][j], a0, a1, a2, a3, blo[j][0], blo[j][1]);
            }
        }
    }
}

// ---------------- moe kernel ----------------
__global__ void __launch_bounds__(NTHREADS, 2)
moe_kernel(const float* __restrict__ cur,
           const float* __restrict__ bl,  const float* __restrict__ bf1,
           const float* __restrict__ bf2, const float* __restrict__ bc1,
           const float* __restrict__ bc2, const float* __restrict__ bg1,
           const float* __restrict__ Wg2, const float* __restrict__ bg2,
           float* __restrict__ out, int out_size) {
    extern __shared__ unsigned smw[];
    float* smf = (float*)smw;
    int*   smi = (int*)smw;

    int tid = threadIdx.x;
    int warp = tid >> 5, lane = tid & 31;
    int g = lane >> 2, tig = lane & 3;
    int base = blockIdx.x * ROWS;
    int nrows = min(ROWS, NCELLS - base);
    int col0 = warp * 8 + tig * 2;

    // ============ prologue: [cur | act] + Wg1 planes + flags ========
    fillLeft(smw, tid, base, nrows);
    fillRight(smw, g_ac, tid, base, nrows);
    loadWp<32>(smw, WOG1, tid);
    if (tid < ROWS)
        smi[tid * PKX + 67] = (base + tid < NCELLS) ? g_flags[base + tid] : 0;
    cp_wait_all();
    __syncthreads();

    // ============ gating ============
    {
        float accg[5][1][4];
        if (warp < 4) mma_gemm<1>(smw, warp, g, tig, accg);
        __syncthreads();                 // plane reads done
        fillRight(smw, g_ml, tid, base, nrows);   // prefetch mean_l
        if (warp < 4) {
            float* Gsf = (float*)(smw + OWH);   // overlay, pitch 33
            int c = warp * 8 + tig * 2;
            float b0 = bg1[c], b1 = bg1[c + 1];
#pragma unroll
            for (int mt = 0; mt < 5; mt++) {
                int r0 = mt * 16 + g, r1 = r0 + 8;
                Gsf[r0 * 33 + c]     = fast_tanh(accg[mt][0][0] + b0);
                Gsf[r0 * 33 + c + 1] = fast_tanh(accg[mt][0][1] + b1);
                Gsf[r1 * 33 + c]     = fast_tanh(accg[mt][0][2] + b0);
                Gsf[r1 * 33 + c + 1] = fast_tanh(accg[mt][0][3] + b1);
            }
        }
        __syncthreads();
        if (tid < ROWS) {
            const float* Gsf = (const float*)(smw + OWH);
            float l0 = bg2[0], l1 = bg2[1], l2 = bg2[2];
#pragma unroll
            for (int k = 0; k < 32; k++) {
                float gv = Gsf[tid * 33 + k];
                l0 += gv * Wg2[k * 3 + 0];
                l1 += gv * Wg2[k * 3 + 1];
                l2 += gv * Wg2[k * 3 + 2];
            }
            float m = fmaxf(l0, fmaxf(l1, l2));
            float e0 = expf(l0 - m), e1 = expf(l1 - m), e2 = expf(l2 - m);
            float inv = 1.0f / (e0 + e1 + e2);
            float w0 = e0 * inv, w1 = e1 * inv, w2 = e2 * inv;
            smf[tid * PKX + 64] = w0;
            smf[tid * PKX + 65] = w1;
            smf[tid * PKX + 66] = w2;
            int gr = base + tid;
            if (gr < NCELLS && out_size >= NCELLS * 67) {
                out[(size_t)NCELLS * 64 + (size_t)gr * 3 + 0] = w0;
                out[(size_t)NCELLS * 64 + (size_t)gr * 3 + 1] = w1;
                out[(size_t)NCELLS * 64 + (size_t)gr * 3 + 2] = w2;
            }
        }
        __syncthreads();                 // Gs reads done -> Ws reusable
        loadWp<64>(smw, WOL, tid);
        cp_wait_all();
        __syncthreads();
    }

    float comb[5][4];

    // ============ local expert ============
    {
        float accl[5][1][4];
        mma_gemm<1>(smw, warp, g, tig, accl);
        __syncthreads();
        fillRight(smw, g_mf, tid, base, nrows);
        loadWp<128>(smw, WOF1, tid);
        float b0v = bl[col0], b1v = bl[col0 + 1];
#pragma unroll
        for (int mt = 0; mt < 5; mt++) {
            int r0 = mt * 16 + g, r1 = r0 + 8;
            float w0a = smf[r0 * PKX + 64]; int f0 = smi[r0 * PKX + 67] & 1;
            float w0b = smf[r1 * PKX + 64]; int f1 = smi[r1 * PKX + 67] & 1;
            comb[mt][0] = f0 ? w0a * fast_tanh(accl[mt][0][0] + b0v) : 0.f;
            comb[mt][1] = f0 ? w0a * fast_tanh(accl[mt][0][1] + b1v) : 0.f;
            comb[mt][2] = f1 ? w0b * fast_tanh(accl[mt][0][2] + b0v) : 0.f;
            comb[mt][3] = f1 ? w0b * fast_tanh(accl[mt][0][3] + b1v) : 0.f;
        }
        cp_wait_all();
        __syncthreads();
    }

    // ============ functional expert L1 ============
    {
        float acch[5][2][4];
        mma_gemm<2>(smw, warp * 2, g, tig, acch);
        __syncthreads();
        loadWp<64>(smw, WOF2, tid);
#pragma unroll
        for (int j = 0; j < 2; j++) {
            int cj = (warp * 2 + j) * 8 + tig * 2;
            float bj0 = bf1[cj], bj1 = bf1[cj + 1];
            int wc = (cj >> 1);
#pragma unroll
            for (int mt = 0; mt < 5; mt++) {
                int r0 = mt * 16 + g, r1 = r0 + 8;
                smw[OXH + r0 * PKX + wc] = fpack(fast_tanh(acch[mt][j][0] + bj0),
                                                fast_tanh(acch[mt][j][1] + bj1));
                smw[OXH + r1 * PKX + wc] = fpack(fast_tanh(acch[mt][j][2] + bj0),
                                                fast_tanh(acch[mt][j][3] + bj1));
            }
        }
        cp_wait_all();
        __syncthreads();
    }

    // ============ functional expert L2 + CNF setup ============
    float x[5][4];
    {
        float accf[5][1][4];
        mma_gemm<1>(smw, warp, g, tig, accf);
        __syncthreads();
        fillRight(smw, g_md, tid, base, nrows);
        loadWp<128>(smw, WOC1, tid);
        float c0v = bf2[col0], c1v = bf2[col0 + 1];
#pragma unroll
        for (int mt = 0; mt < 5; mt++) {
            int r0 = mt * 16 + g, r1 = r0 + 8;
            float w1a = smf[r0 * PKX + 65]; int f0 = smi[r0 * PKX + 67] & 2;
            float w1b = smf[r1 * PKX + 65]; int f1 = smi[r1 * PKX + 67] & 2;
            comb[mt][0] += f0 ? w1a * fast_tanh(accf[mt][0][0] + c0v) : 0.f;
            comb[mt][1] += f0 ? w1a * fast_tanh(accf[mt][0][1] + c1v) : 0.f;
            comb[mt][2] += f1 ? w1b * fast_tanh(accf[mt][0][2] + c0v) : 0.f;
            comb[mt][3] += f1 ? w1b * fast_tanh(accf[mt][0][3] + c1v) : 0.f;
            // park comb in out (each thread owns these cells exclusively)
            int gr0 = base + r0, gr1 = base + r1;
            if (gr0 < NCELLS)
                *(float2*)&out[(size_t)gr0 * 64 + col0] = make_float2(comb[mt][0], comb[mt][1]);
            if (gr1 < NCELLS)
                *(float2*)&out[(size_t)gr1 * 64 + col0] = make_float2(comb[mt][2], comb[mt][3]);
        }
        // CNF x init + stage into Xs left half
        int wcl = warp * 4 + tig;
#pragma unroll
        for (int mt = 0; mt < 5; mt++) {
            int r0 = mt * 16 + g, r1 = r0 + 8;
            int gr0 = base + r0, gr1 = base + r1;
            float2 v0 = (gr0 < NCELLS) ? *(const float2*)(cur + (size_t)gr0 * 64 + col0)
                                       : make_float2(0.f, 0.f);
            float2 v1 = (gr1 < NCELLS) ? *(const float2*)(cur + (size_t)gr1 * 64 + col0)
                                       : make_float2(0.f, 0.f);
            x[mt][0] = v0.x; x[mt][1] = v0.y; x[mt][2] = v1.x; x[mt][3] = v1.y;
            smw[OXH + r0 * PKX + wcl] = fpack(v0.x, v0.y);
            smw[OXH + r1 * PKX + wcl] = fpack(v1.x, v1.y);
        }
        cp_wait_all();
        __syncthreads();
    }

    // ============ distant expert: CNF 3 Euler steps ============
    const float DT = 1.0f / 3.0f;
    for (int step = 0; step < 3; step++) {
        {
            float accv[5][2][4];
            mma_gemm<2>(smw, warp * 2, g, tig, accv);
            __syncthreads();
            loadWp<64>(smw, WOC2, tid);
#pragma unroll
            for (int j = 0; j < 2; j++) {
                int cj = (warp * 2 + j) * 8 + tig * 2;
                float bj0 = bc1[cj], bj1 = bc1[cj + 1];
                int wc = (cj >> 1);
#pragma unroll
                for (int mt = 0; mt < 5; mt++) {
                    int r0 = mt * 16 + g, r1 = r0 + 8;
                    smw[OXH + r0 * PKX + wc] = fpack(fast_tanh(accv[mt][j][0] + bj0),
                                                    fast_tanh(accv[mt][j][1] + bj1));
                    smw[OXH + r1 * PKX + wc] = fpack(fast_tanh(accv[mt][j][2] + bj0),
                                                    fast_tanh(accv[mt][j][3] + bj1));
                }
            }
            cp_wait_all();
            __syncthreads();
        }
        {
            float accd[5][1][4];
            mma_gemm<1>(smw, warp, g, tig, accd);
            __syncthreads();
            if (step < 2) {
                loadWp<128>(smw, WOC1, tid);
                fillRight(smw, g_md, tid, base, nrows);
            }
            float bb0 = bc2[col0], bb1 = bc2[col0 + 1];
#pragma unroll
            for (int mt = 0; mt < 5; mt++) {
                x[mt][0] += DT * fast_tanh(accd[mt][0][0] + bb0);
                x[mt][1] += DT * fast_tanh(accd[mt][0][1] + bb1);
                x[mt][2] += DT * fast_tanh(accd[mt][0][2] + bb0);
                x[mt][3] += DT * fast_tanh(accd[mt][0][3] + bb1);
            }
            if (step < 2) {
                int wcl = warp * 4 + tig;
#pragma unroll
                for (int mt = 0; mt < 5; mt++) {
                    int r0 = mt * 16 + g, r1 = r0 + 8;
                    smw[OXH + r0 * PKX + wcl] = fpack(x[mt][0], x[mt][1]);
                    smw[OXH + r1 * PKX + wcl] = fpack(x[mt][2], x[mt][3]);
                }
                cp_wait_all();
                __syncthreads();
            }
        }
    }

    // ============ unpark comb, add CNF term, store ============
#pragma unroll
    for (int mt = 0; mt < 5; mt++) {
        int r0 = mt * 16 + g, r1 = r0 + 8;
        float w2a = smf[r0 * PKX + 66]; int f0 = smi[r0 * PKX + 67] & 4;
        float w2b = smf[r1 * PKX + 66]; int f1 = smi[r1 * PKX + 67] & 4;
        int gr0 = base + r0, gr1 = base + r1;
        if (gr0 < NCELLS) {
            float2 o = *(const float2*)&out[(size_t)gr0 * 64 + col0];
            o.x += f0 ? w2a * x[mt][0] : 0.f;
            o.y += f0 ? w2a * x[mt][1] : 0.f;
            *(float2*)&out[(size_t)gr0 * 64 + col0] = o;
        }
        if (gr1 < NCELLS) {
            float2 o = *(const float2*)&out[(size_t)gr1 * 64 + col0];
            o.x += f1 ? w2b * x[mt][2] : 0.f;
            o.y += f1 ? w2b * x[mt][3] : 0.f;
            *(float2*)&out[(size_t)gr1 * 64 + col0] = o;
        }
    }
}

// ---------------- launch ----------------
extern "C" void kernel_launch(void* const* d_in, const int* in_sizes, int n_in,
                              void* d_out, int out_size) {
    const float* cur = (const float*)d_in[0];
    const float* nb  = (const float*)d_in[1];
    const int*   cat = (const int*)d_in[2];
    const float* Wl  = (const float*)d_in[3];
    const float* bl  = (const float*)d_in[4];
    const float* Wf1 = (const float*)d_in[5];
    const float* bf1 = (const float*)d_in[6];
    const float* Wf2 = (const float*)d_in[7];
    const float* bf2 = (const float*)d_in[8];
    const float* Wc1 = (const float*)d_in[9];
    const float* bc1 = (const float*)d_in[10];
    const float* Wc2 = (const float*)d_in[11];
    const float* bc2 = (const float*)d_in[12];
    const float* Wg1 = (const float*)d_in[13];
    const float* bg1 = (const float*)d_in[14];
    const float* Wg2 = (const float*)d_in[15];
    const float* bg2 = (const float*)d_in[16];
    float* out = (float*)d_out;

    const int smem_bytes = SMW_TOTAL * 4;   // 91,392 B
    cudaFuncSetAttribute(moe_kernel, cudaFuncAttributeMaxDynamicSharedMemorySize,
                         smem_bytes);

    pre_kernel<<<PREPB + AGGB, 256>>>(cur, Wg1, Wl, Wf1, Wf2, Wc1, Wc2, nb, cat);

    int moe_blocks = (NCELLS + ROWS - 1) / ROWS;   // 247 -> single wave at 2 CTA/SM
    moe_kernel<<<moe_blocks, NTHREADS, smem_bytes>>>(
        cur, bl, bf1, bf2, bc1, bc2, bg1, Wg2, bg2, out, out_size);
}

// round 17
// speedup vs baseline: 2.3825x; 1.1433x over previous
#include <cuda_runtime.h>
#include <cuda_fp16.h>

#define NCELLS   19683
#define KNB      26
#define ROWS     80    // rows per CTA tile -> grid 247 (single wave @ 2 CTA/SM)
#define NTHREADS 256
#define PKX      68    // Xs row pitch (32-bit words; 64 data + 4 pad: sw+flag)
#define PKW      68    // Ws row pitch (words; mult-of-4 for cp.async 16B)

// smem word offsets (fp16: A single plane, B single plane)
#define OXH 0
#define OWH 5440          // 80*68
#define SMW_TOTAL 14144   // 5440 + 128*68 -> 56,576 bytes

// weight-plane word offsets in global scratch
#define WOG1 0
#define WOL  2048
#define WOF1 6144
#define WOF2 14336
#define WOC1 18432
#define WOC2 26624
#define WTOT 30720

#define CURW (19683 * 32)
#define PREPB 2581        // prep blocks: ceil((CURW + WTOT)/256)
#define AGGB  2461        // agg blocks:  ceil(NCELLS*32/256)

// ---------------- global scratch (allocation-free) ----------------
__device__ unsigned g_cur[CURW];            // fp16x2 activations
__device__ unsigned g_ml[CURW], g_mf[CURW], g_md[CURW], g_ac[CURW];
__device__ unsigned g_wH[WTOT];             // weights: single fp16 plane
__device__ int      g_flags[NCELLS];

// ---------------- helpers ----------------
__device__ __forceinline__ float fast_tanh(float x) {
    float ax = fabsf(x);
    float t  = __expf(-2.0f * ax);
    float r  = __fdividef(1.0f - t, 1.0f + t);
    return copysignf(r, x);
}

__device__ __forceinline__ unsigned fpack(float x0, float x1) {
    __half2 h = __floats2half2_rn(x0, x1);
    return *reinterpret_cast<unsigned*>(&h);
}

__device__ __forceinline__ void mma4(float (&c)[4], unsigned a0, unsigned a1,
                                     unsigned a2, unsigned a3, unsigned b0, unsigned b1) {
    asm("mma.sync.aligned.m16n8k16.row.col.f32.f16.f16.f32 "
        "{%0,%1,%2,%3},{%4,%5,%6,%7},{%8,%9},{%0,%1,%2,%3};"
        : "+f"(c[0]), "+f"(c[1]), "+f"(c[2]), "+f"(c[3])
        : "r"(a0), "r"(a1), "r"(a2), "r"(a3), "r"(b0), "r"(b1));
}

__device__ __forceinline__ void cpa16(void* s, const void* g) {
    unsigned sa = (unsigned)__cvta_generic_to_shared(s);
    asm volatile("cp.async.ca.shared.global [%0], [%1], 16;" :: "r"(sa), "l"(g));
}
__device__ __forceinline__ void cp_wait_all() {
    asm volatile("cp.async.wait_all;" ::: "memory");
}

// ---------------- fused pre kernel: prep (blocks < PREPB) + agg ------------
__global__ void pre_kernel(const float* __restrict__ cur,
                           const float* __restrict__ Wg1, const float* __restrict__ Wl,
                           const float* __restrict__ Wf1, const float* __restrict__ Wf2,
                           const float* __restrict__ Wc1, const float* __restrict__ Wc2,
                           const float* __restrict__ nb,  const int* __restrict__ cat) {
    if (blockIdx.x < PREPB) {
        int idx = blockIdx.x * blockDim.x + threadIdx.x;
        if (idx < CURW) {
            int k2 = idx & 31; int row = idx >> 5;
            float2 v = *(const float2*)(cur + (size_t)row * 64 + k2 * 2);
            g_cur[idx] = fpack(v.x, v.y);
            return;
        }
        int j = idx - CURW;
        const float* W; int NC; int off;
        if (j < 2048)                { W = Wg1; NC = 32;  off = WOG1; }
        else if ((j -= 2048) < 4096) { W = Wl;  NC = 64;  off = WOL;  }
        else if ((j -= 4096) < 8192) { W = Wf1; NC = 128; off = WOF1; }
        else if ((j -= 8192) < 4096) { W = Wf2; NC = 64;  off = WOF2; }
        else if ((j -= 4096) < 8192) { W = Wc1; NC = 128; off = WOC1; }
        else if ((j -= 8192) < 4096) { W = Wc2; NC = 64;  off = WOC2; }
        else return;
        int k2 = j / NC; int n = j - k2 * NC;
        float w0 = W[(2 * k2) * NC + n];
        float w1 = W[(2 * k2 + 1) * NC + n];
        g_wH[off + n * 64 + k2] = fpack(w0, w1);   // transposed: row n holds contiguous k
        return;
    }
    // ---- agg part ----
    int gw = ((blockIdx.x - PREPB) * blockDim.x + threadIdx.x) >> 5;
    if (gw >= NCELLS) return;
    int lane = threadIdx.x & 31;
    const float* base = nb + (size_t)gw * (KNB * 64);
    int myc = (lane < KNB) ? cat[gw * KNB + lane] : -1;

    unsigned m0 = __ballot_sync(0xffffffffu, myc == 0);
    unsigned m1 = __ballot_sync(0xffffffffu, myc == 1);
    unsigned m2 = __ballot_sync(0xffffffffu, myc == 2);

    float2 s0 = {0.f, 0.f}, s1 = {0.f, 0.f}, s2 = {0.f, 0.f}, sa = {0.f, 0.f};
#pragma unroll
    for (int k = 0; k < KNB; k++) {
        float2 v = *(const float2*)(base + k * 64 + lane * 2);
        sa.x += v.x; sa.y += v.y;
        bool b0 = (m0 >> k) & 1u;
        bool b1 = (m1 >> k) & 1u;
        bool b2 = (m2 >> k) & 1u;
        s0.x += b0 ? v.x : 0.f;  s0.y += b0 ? v.y : 0.f;
        s1.x += b1 ? v.x : 0.f;  s1.y += b1 ? v.y : 0.f;
        s2.x += b2 ? v.x : 0.f;  s2.y += b2 ? v.y : 0.f;
    }
    int c0 = __popc(m0), c1 = __popc(m1), c2 = __popc(m2);
    float d0 = fmaxf((float)c0, 1.0f);
    float d1 = fmaxf((float)c1, 1.0f);
    float d2 = fmaxf((float)c2, 1.0f);
    int off = gw * 32 + lane;
    g_ml[off] = fpack(s0.x / d0, s0.y / d0);
    g_mf[off] = fpack(s1.x / d1, s1.y / d1);
    g_md[off] = fpack(s2.x / d2, s2.y / d2);
    g_ac[off] = fpack(sa.x / 26.0f, sa.y / 26.0f);
    if (lane == 0)
        g_flags[gw] = (c0 > 0 ? 1 : 0) | (c1 > 0 ? 2 : 0) | (c2 > 0 ? 4 : 0);
}

// ---------------- moe helpers ----------------
__device__ __forceinline__ void fillLeft(unsigned* smw, int tid, int base, int nrows) {
    for (int i = tid; i < ROWS * 8; i += NTHREADS) {
        int r = i >> 3, c = i & 7;
        int gr = base + ((r < nrows) ? r : 0);
        cpa16(smw + OXH + r * PKX + c * 4, g_cur + (size_t)gr * 32 + c * 4);
    }
}
__device__ __forceinline__ void fillRight(unsigned* smw, const unsigned* __restrict__ src,
                                          int tid, int base, int nrows) {
    for (int i = tid; i < ROWS * 8; i += NTHREADS) {
        int r = i >> 3, c = i & 7;
        int gr = base + ((r < nrows) ? r : 0);
        cpa16(smw + OXH + r * PKX + 32 + c * 4, src + (size_t)gr * 32 + c * 4);
    }
}
template <int NC>
__device__ __forceinline__ void loadWp(unsigned* smw, int off, int tid) {
    for (int i = tid; i < NC * 16; i += NTHREADS) {
        int r = i >> 4, c = i & 15;
        cpa16(smw + OWH + r * PKW + c * 4, g_wH + off + r * 64 + c * 4);
    }
}

// pure fp16 MMA GEMM: 80 x (NT*8 per warp) x 128, one MMA per tile
template <int NT>
__device__ __forceinline__ void mma_gemm(const unsigned* __restrict__ smw,
                                         int nt0, int g, int tig, float (&acc)[5][NT][4]) {
#pragma unroll
    for (int mt = 0; mt < 5; mt++)
#pragma unroll
        for (int j = 0; j < NT; j++)
#pragma unroll
            for (int k = 0; k < 4; k++) acc[mt][j][k] = 0.f;

    const unsigned* XH = smw + OXH;
    const unsigned* WH = smw + OWH;
#pragma unroll
    for (int ks = 0; ks < 8; ks++) {
        unsigned bh[NT][2];
#pragma unroll
        for (int j = 0; j < NT; j++) {
            int wr = ((nt0 + j) * 8 + g) * PKW + ks * 8 + tig;
            bh[j][0] = WH[wr]; bh[j][1] = WH[wr + 4];
        }
#pragma unroll
        for (int mt = 0; mt < 5; mt++) {
            int xr = (mt * 16 + g) * PKX + ks * 8 + tig;
            unsigned a0 = XH[xr], a1 = XH[xr + 8 * PKX], a2 = XH[xr + 4], a3 = XH[xr + 8 * PKX + 4];
#pragma unroll
            for (int j = 0; j < NT; j++)
                mma4(acc[mt][j], a0, a1, a2, a3, bh[j][0], bh[j][1]);
        }
    }
}

// ---------------- moe kernel ----------------
__global__ void __launch_bounds__(NTHREADS, 2)
moe_kernel(const float* __restrict__ cur,
           const float* __restrict__ bl,  const float* __restrict__ bf1,
           const float* __restrict__ bf2, const float* __restrict__ bc1,
           const float* __restrict__ bc2, const float* __restrict__ bg1,
           const float* __restrict__ Wg2, const float* __restrict__ bg2,
           float* __restrict__ out, int out_size) {
    extern __shared__ unsigned smw[];
    float* smf = (float*)smw;
    int*   smi = (int*)smw;

    int tid = threadIdx.x;
    int warp = tid >> 5, lane = tid & 31;
    int g = lane >> 2, tig = lane & 3;
    int base = blockIdx.x * ROWS;
    int nrows = min(ROWS, NCELLS - base);
    int col0 = warp * 8 + tig * 2;

    // ============ prologue: [cur | act] + Wg1 plane + flags ========
    fillLeft(smw, tid, base, nrows);
    fillRight(smw, g_ac, tid, base, nrows);
    loadWp<32>(smw, WOG1, tid);
    if (tid < ROWS)
        smi[tid * PKX + 67] = (base + tid < NCELLS) ? g_flags[base + tid] : 0;
    cp_wait_all();
    __syncthreads();

    // ============ gating ============
    {
        float accg[5][1][4];
        if (warp < 4) mma_gemm<1>(smw, warp, g, tig, accg);
        __syncthreads();                 // plane reads done
        fillRight(smw, g_ml, tid, base, nrows);   // prefetch mean_l
        if (warp < 4) {
            float* Gsf = (float*)(smw + OWH);   // overlay, pitch 33
            int c = warp * 8 + tig * 2;
            float b0 = bg1[c], b1 = bg1[c + 1];
#pragma unroll
            for (int mt = 0; mt < 5; mt++) {
                int r0 = mt * 16 + g, r1 = r0 + 8;
                Gsf[r0 * 33 + c]     = fast_tanh(accg[mt][0][0] + b0);
                Gsf[r0 * 33 + c + 1] = fast_tanh(accg[mt][0][1] + b1);
                Gsf[r1 * 33 + c]     = fast_tanh(accg[mt][0][2] + b0);
                Gsf[r1 * 33 + c + 1] = fast_tanh(accg[mt][0][3] + b1);
            }
        }
        __syncthreads();
        if (tid < ROWS) {
            const float* Gsf = (const float*)(smw + OWH);
            float l0 = bg2[0], l1 = bg2[1], l2 = bg2[2];
#pragma unroll
            for (int k = 0; k < 32; k++) {
                float gv = Gsf[tid * 33 + k];
                l0 += gv * Wg2[k * 3 + 0];
                l1 += gv * Wg2[k * 3 + 1];
                l2 += gv * Wg2[k * 3 + 2];
            }
            float m = fmaxf(l0, fmaxf(l1, l2));
            float e0 = expf(l0 - m), e1 = expf(l1 - m), e2 = expf(l2 - m);
            float inv = 1.0f / (e0 + e1 + e2);
            float w0 = e0 * inv, w1 = e1 * inv, w2 = e2 * inv;
            smf[tid * PKX + 64] = w0;
            smf[tid * PKX + 65] = w1;
            smf[tid * PKX + 66] = w2;
            int gr = base + tid;
            if (gr < NCELLS && out_size >= NCELLS * 67) {
                out[(size_t)NCELLS * 64 + (size_t)gr * 3 + 0] = w0;
                out[(size_t)NCELLS * 64 + (size_t)gr * 3 + 1] = w1;
                out[(size_t)NCELLS * 64 + (size_t)gr * 3 + 2] = w2;
            }
        }
        __syncthreads();                 // Gs reads done -> Ws reusable
        loadWp<64>(smw, WOL, tid);
        cp_wait_all();
        __syncthreads();
    }

    float comb[5][4];

    // ============ local expert ============
    {
        float accl[5][1][4];
        mma_gemm<1>(smw, warp, g, tig, accl);
        __syncthreads();
        fillRight(smw, g_mf, tid, base, nrows);
        loadWp<128>(smw, WOF1, tid);
        float b0v = bl[col0], b1v = bl[col0 + 1];
#pragma unroll
        for (int mt = 0; mt < 5; mt++) {
            int r0 = mt * 16 + g, r1 = r0 + 8;
            float w0a = smf[r0 * PKX + 64]; int f0 = smi[r0 * PKX + 67] & 1;
            float w0b = smf[r1 * PKX + 64]; int f1 = smi[r1 * PKX + 67] & 1;
            comb[mt][0] = f0 ? w0a * fast_tanh(accl[mt][0][0] + b0v) : 0.f;
            comb[mt][1] = f0 ? w0a * fast_tanh(accl[mt][0][1] + b1v) : 0.f;
            comb[mt][2] = f1 ? w0b * fast_tanh(accl[mt][0][2] + b0v) : 0.f;
            comb[mt][3] = f1 ? w0b * fast_tanh(accl[mt][0][3] + b1v) : 0.f;
        }
        cp_wait_all();
        __syncthreads();
    }

    // ============ functional expert L1 ============
    {
        float acch[5][2][4];
        mma_gemm<2>(smw, warp * 2, g, tig, acch);
        __syncthreads();
        loadWp<64>(smw, WOF2, tid);
#pragma unroll
        for (int j = 0; j < 2; j++) {
            int cj = (warp * 2 + j) * 8 + tig * 2;
            float bj0 = bf1[cj], bj1 = bf1[cj + 1];
            int wc = (cj >> 1);
#pragma unroll
            for (int mt = 0; mt < 5; mt++) {
                int r0 = mt * 16 + g, r1 = r0 + 8;
                smw[OXH + r0 * PKX + wc] = fpack(fast_tanh(acch[mt][j][0] + bj0),
                                                fast_tanh(acch[mt][j][1] + bj1));
                smw[OXH + r1 * PKX + wc] = fpack(fast_tanh(acch[mt][j][2] + bj0),
                                                fast_tanh(acch[mt][j][3] + bj1));
            }
        }
        cp_wait_all();
        __syncthreads();
    }

    // ============ functional expert L2 + CNF setup ============
    float x[5][4];
    {
        float accf[5][1][4];
        mma_gemm<1>(smw, warp, g, tig, accf);
        __syncthreads();
        fillRight(smw, g_md, tid, base, nrows);
        loadWp<128>(smw, WOC1, tid);
        float c0v = bf2[col0], c1v = bf2[col0 + 1];
#pragma unroll
        for (int mt = 0; mt < 5; mt++) {
            int r0 = mt * 16 + g, r1 = r0 + 8;
            float w1a = smf[r0 * PKX + 65]; int f0 = smi[r0 * PKX + 67] & 2;
            float w1b = smf[r1 * PKX + 65]; int f1 = smi[r1 * PKX + 67] & 2;
            comb[mt][0] += f0 ? w1a * fast_tanh(accf[mt][0][0] + c0v) : 0.f;
            comb[mt][1] += f0 ? w1a * fast_tanh(accf[mt][0][1] + c1v) : 0.f;
            comb[mt][2] += f1 ? w1b * fast_tanh(accf[mt][0][2] + c0v) : 0.f;
            comb[mt][3] += f1 ? w1b * fast_tanh(accf[mt][0][3] + c1v) : 0.f;
            // park comb in out (each thread owns these cells exclusively)
            int gr0 = base + r0, gr1 = base + r1;
            if (gr0 < NCELLS)
                *(float2*)&out[(size_t)gr0 * 64 + col0] = make_float2(comb[mt][0], comb[mt][1]);
            if (gr1 < NCELLS)
                *(float2*)&out[(size_t)gr1 * 64 + col0] = make_float2(comb[mt][2], comb[mt][3]);
        }
        // CNF x init + stage into Xs left half
        int wcl = warp * 4 + tig;
#pragma unroll
        for (int mt = 0; mt < 5; mt++) {
            int r0 = mt * 16 + g, r1 = r0 + 8;
            int gr0 = base + r0, gr1 = base + r1;
            float2 v0 = (gr0 < NCELLS) ? *(const float2*)(cur + (size_t)gr0 * 64 + col0)
                                       : make_float2(0.f, 0.f);
            float2 v1 = (gr1 < NCELLS) ? *(const float2*)(cur + (size_t)gr1 * 64 + col0)
                                       : make_float2(0.f, 0.f);
            x[mt][0] = v0.x; x[mt][1] = v0.y; x[mt][2] = v1.x; x[mt][3] = v1.y;
            smw[OXH + r0 * PKX + wcl] = fpack(v0.x, v0.y);
            smw[OXH + r1 * PKX + wcl] = fpack(v1.x, v1.y);
        }
        cp_wait_all();
        __syncthreads();
    }

    // ============ distant expert: CNF 3 Euler steps ============
    const float DT = 1.0f / 3.0f;
    for (int step = 0; step < 3; step++) {
        {
            float accv[5][2][4];
            mma_gemm<2>(smw, warp * 2, g, tig, accv);
            __syncthreads();
            loadWp<64>(smw, WOC2, tid);
#pragma unroll
            for (int j = 0; j < 2; j++) {
                int cj = (warp * 2 + j) * 8 + tig * 2;
                float bj0 = bc1[cj], bj1 = bc1[cj + 1];
                int wc = (cj >> 1);
#pragma unroll
                for (int mt = 0; mt < 5; mt++) {
                    int r0 = mt * 16 + g, r1 = r0 + 8;
                    smw[OXH + r0 * PKX + wc] = fpack(fast_tanh(accv[mt][j][0] + bj0),
                                                    fast_tanh(accv[mt][j][1] + bj1));
                    smw[OXH + r1 * PKX + wc] = fpack(fast_tanh(accv[mt][j][2] + bj0),
                                                    fast_tanh(accv[mt][j][3] + bj1));
                }
            }
            cp_wait_all();
            __syncthreads();
        }
        {
            float accd[5][1][4];
            mma_gemm<1>(smw, warp, g, tig, accd);
            __syncthreads();
            if (step < 2) {
                loadWp<128>(smw, WOC1, tid);
                fillRight(smw, g_md, tid, base, nrows);
            }
            float bb0 = bc2[col0], bb1 = bc2[col0 + 1];
#pragma unroll
            for (int mt = 0; mt < 5; mt++) {
                x[mt][0] += DT * fast_tanh(accd[mt][0][0] + bb0);
                x[mt][1] += DT * fast_tanh(accd[mt][0][1] + bb1);
                x[mt][2] += DT * fast_tanh(accd[mt][0][2] + bb0);
                x[mt][3] += DT * fast_tanh(accd[mt][0][3] + bb1);
            }
            if (step < 2) {
                int wcl = warp * 4 + tig;
#pragma unroll
                for (int mt = 0; mt < 5; mt++) {
                    int r0 = mt * 16 + g, r1 = r0 + 8;
                    smw[OXH + r0 * PKX + wcl] = fpack(x[mt][0], x[mt][1]);
                    smw[OXH + r1 * PKX + wcl] = fpack(x[mt][2], x[mt][3]);
                }
                cp_wait_all();
                __syncthreads();
            }
        }
    }

    // ============ unpark comb, add CNF term, store ============
#pragma unroll
    for (int mt = 0; mt < 5; mt++) {
        int r0 = mt * 16 + g, r1 = r0 + 8;
        float w2a = smf[r0 * PKX + 66]; int f0 = smi[r0 * PKX + 67] & 4;
        float w2b = smf[r1 * PKX + 66]; int f1 = smi[r1 * PKX + 67] & 4;
        int gr0 = base + r0, gr1 = base + r1;
        if (gr0 < NCELLS) {
            float2 o = *(const float2*)&out[(size_t)gr0 * 64 + col0];
            o.x += f0 ? w2a * x[mt][0] : 0.f;
            o.y += f0 ? w2a * x[mt][1] : 0.f;
            *(float2*)&out[(size_t)gr0 * 64 + col0] = o;
        }
        if (gr1 < NCELLS) {
            float2 o = *(const float2*)&out[(size_t)gr1 * 64 + col0];
            o.x += f1 ? w2b * x[mt][2] : 0.f;
            o.y += f1 ? w2b * x[mt][3] : 0.f;
            *(float2*)&out[(size_t)gr1 * 64 + col0] = o;
        }
    }
}

// ---------------- launch ----------------
extern "C" void kernel_launch(void* const* d_in, const int* in_sizes, int n_in,
                              void* d_out, int out_size) {
    const float* cur = (const float*)d_in[0];
    const float* nb  = (const float*)d_in[1];
    const int*   cat = (const int*)d_in[2];
    const float* Wl  = (const float*)d_in[3];
    const float* bl  = (const float*)d_in[4];
    const float* Wf1 = (const float*)d_in[5];
    const float* bf1 = (const float*)d_in[6];
    const float* Wf2 = (const float*)d_in[7];
    const float* bf2 = (const float*)d_in[8];
    const float* Wc1 = (const float*)d_in[9];
    const float* bc1 = (const float*)d_in[10];
    const float* Wc2 = (const float*)d_in[11];
    const float* bc2 = (const float*)d_in[12];
    const float* Wg1 = (const float*)d_in[13];
    const float* bg1 = (const float*)d_in[14];
    const float* Wg2 = (const float*)d_in[15];
    const float* bg2 = (const float*)d_in[16];
    float* out = (float*)d_out;

    const int smem_bytes = SMW_TOTAL * 4;   // 56,576 B
    cudaFuncSetAttribute(moe_kernel, cudaFuncAttributeMaxDynamicSharedMemorySize,
                         smem_bytes);

    pre_kernel<<<PREPB + AGGB, 256>>>(cur, Wg1, Wl, Wf1, Wf2, Wc1, Wc2, nb, cat);

    int moe_blocks = (NCELLS + ROWS - 1) / ROWS;   // 247 -> single wave at 2 CTA/SM
    moe_kernel<<<moe_blocks, NTHREADS, smem_bytes>>>(
        cur, bl, bf1, bf2, bc1, bc2, bg1, Wg2, bg2, out, out_size);
}